// round 5
// baseline (speedup 1.0000x reference)
#include <cuda_runtime.h>
#include <math.h>
#include <stdint.h>

#define Bn   2
#define Sn   4096
#define Dn   512
#define Hn   8
#define DKn  64
#define DFFn 2048
#define Mrows (Bn*Sn)   /* 8192 */

// ---------------- scratch (no allocs allowed) ----------------
__device__ float g_q[Bn*Hn*Sn*DKn];     // [B,H,S,DK]
__device__ float g_k[Bn*Hn*Sn*DKn];
__device__ float g_v[Bn*Hn*Sn*DKn];
__device__ float g_ctx[Mrows*Dn];       // [B,S,D]
__device__ float g_res1[Mrows*Dn];
__device__ float g_x1[Mrows*Dn];
__device__ float g_ff[Mrows*DFFn];

// ---------------- packed f32x2 helpers ----------------
typedef unsigned long long u64t;

__device__ __forceinline__ u64t pack2(float lo, float hi) {
    u64t r;
    asm("mov.b64 %0, {%1, %2};" : "=l"(r) : "f"(lo), "f"(hi));
    return r;
}
__device__ __forceinline__ void unpack2(u64t v, float& lo, float& hi) {
    asm("mov.b64 {%0, %1}, %2;" : "=f"(lo), "=f"(hi) : "l"(v));
}
__device__ __forceinline__ u64t fma2(u64t a, u64t b, u64t c) {
    u64t d;
    asm("fma.rn.f32x2 %0, %1, %2, %3;" : "=l"(d) : "l"(a), "l"(b), "l"(c));
    return d;
}
__device__ __forceinline__ u64t mul2(u64t a, u64t b) {
    u64t d;
    asm("mul.rn.f32x2 %0, %1, %2;" : "=l"(d) : "l"(a), "l"(b));
    return d;
}

// ---------------- GEMM: C[M,N] = A[M,K] @ W[K,N] + epilogue ----------------
// 128x128 block tile, BK=32, 256 threads, 8x8 microtile, f32x2 packed FMA,
// double-buffered smem with register prefetch (1 sync per K-tile).
#define EPI_QKV       0
#define EPI_RES       1
#define EPI_BIAS_RELU 2
#define EPI_BIAS_RES  3

#define GEMM_SMEM (4 * 32 * 132 * 4)  /* 67584 bytes: 2 stages x (As+Bs) */

template<int N, int K, int EPI>
__global__ __launch_bounds__(256, 2)
void gemm_kernel(const float* __restrict__ A, const float* __restrict__ W,
                 const float* __restrict__ bias, const float* __restrict__ res,
                 float* __restrict__ out)
{
    extern __shared__ float gsm[];
    float* AsBuf[2] = { gsm,            gsm + 2*32*132 };
    float* BsBuf[2] = { gsm + 32*132,   gsm + 3*32*132 };

    const int tid = threadIdx.x;
    const int tx = tid & 15, ty = tid >> 4;
    const int row0 = blockIdx.y * 128;
    const int col0 = blockIdx.x * 128;

    // A tile load: 2 threads/row, 16 floats each (4 float4 along K)
    const int ar  = tid >> 1;
    const int akc = (tid & 1) * 16;
    // B tile load: 8 threads/row, 16 floats each (4 float4 along N)
    const int bkk = tid >> 3;
    const int bnc = (tid & 7) * 16;

    const float* Abase = A + (size_t)(row0 + ar) * K + akc;
    const float* Wbase = W + (size_t)bkk * N + col0 + bnc;

    u64t acc2[8][4];
    #pragma unroll
    for (int i = 0; i < 8; i++)
        #pragma unroll
        for (int jj = 0; jj < 4; jj++) acc2[i][jj] = 0ull;

    float4 aR[4], bR[4];

    // prologue: tile 0 -> regs -> stage 0
    {
        const float4* Ag = (const float4*)Abase;
        const float4* Bg = (const float4*)Wbase;
        #pragma unroll
        for (int c = 0; c < 4; c++) { aR[c] = Ag[c]; bR[c] = Bg[c]; }
        float* As = AsBuf[0];
        float* Bs = BsBuf[0];
        #pragma unroll
        for (int c = 0; c < 4; c++) {
            As[(akc + c*4 + 0)*132 + ar] = aR[c].x;
            As[(akc + c*4 + 1)*132 + ar] = aR[c].y;
            As[(akc + c*4 + 2)*132 + ar] = aR[c].z;
            As[(akc + c*4 + 3)*132 + ar] = aR[c].w;
            *(float4*)&Bs[bkk*132 + bnc + c*4] = bR[c];
        }
    }
    __syncthreads();

    const int NT = K / 32;
    for (int it = 0; it < NT; it++) {
        // issue next tile's global loads early
        if (it + 1 < NT) {
            const float4* Ag = (const float4*)(Abase + (it + 1) * 32);
            const float4* Bg = (const float4*)(Wbase + (size_t)(it + 1) * 32 * N);
            #pragma unroll
            for (int c = 0; c < 4; c++) { aR[c] = Ag[c]; bR[c] = Bg[c]; }
        }

        const float* As = AsBuf[it & 1];
        const float* Bs = BsBuf[it & 1];
        #pragma unroll 8
        for (int kk = 0; kk < 32; kk++) {
            float a[8];
            *(float4*)&a[0] = *(const float4*)&As[kk*132 + ty*8];
            *(float4*)&a[4] = *(const float4*)&As[kk*132 + ty*8 + 4];
            ulonglong2 b01 = *(const ulonglong2*)&Bs[kk*132 + tx*8];
            ulonglong2 b23 = *(const ulonglong2*)&Bs[kk*132 + tx*8 + 4];
            u64t bb[4] = {b01.x, b01.y, b23.x, b23.y};
            #pragma unroll
            for (int i = 0; i < 8; i++) {
                u64t ad = pack2(a[i], a[i]);
                #pragma unroll
                for (int jj = 0; jj < 4; jj++)
                    acc2[i][jj] = fma2(ad, bb[jj], acc2[i][jj]);
            }
        }

        if (it + 1 < NT) {
            float* Asn = AsBuf[(it + 1) & 1];
            float* Bsn = BsBuf[(it + 1) & 1];
            #pragma unroll
            for (int c = 0; c < 4; c++) {
                Asn[(akc + c*4 + 0)*132 + ar] = aR[c].x;
                Asn[(akc + c*4 + 1)*132 + ar] = aR[c].y;
                Asn[(akc + c*4 + 2)*132 + ar] = aR[c].z;
                Asn[(akc + c*4 + 3)*132 + ar] = aR[c].w;
                *(float4*)&Bsn[bkk*132 + bnc + c*4] = bR[c];
            }
        }
        __syncthreads();
    }

    // epilogue
    #pragma unroll
    for (int i = 0; i < 8; i++) {
        const int r  = row0 + ty*8 + i;
        const int c0 = col0 + tx*8;
        float cv[8];
        #pragma unroll
        for (int jj = 0; jj < 4; jj++) unpack2(acc2[i][jj], cv[2*jj], cv[2*jj+1]);

        if (EPI == EPI_QKV) {
            const int b = r >> 12, s = r & (Sn - 1);
            const int h = c0 >> 6, dk = c0 & 63;
            float* dst = out + (((size_t)b * Hn + h) * Sn + s) * DKn + dk;
            *(float4*)dst       = make_float4(cv[0], cv[1], cv[2], cv[3]);
            *(float4*)(dst + 4) = make_float4(cv[4], cv[5], cv[6], cv[7]);
        } else if (EPI == EPI_RES) {
            const float* rp = res + (size_t)r * N + c0;
            float4 r0 = *(const float4*)rp, r1 = *(const float4*)(rp + 4);
            float* dst = out + (size_t)r * N + c0;
            *(float4*)dst       = make_float4(cv[0]+r0.x, cv[1]+r0.y, cv[2]+r0.z, cv[3]+r0.w);
            *(float4*)(dst + 4) = make_float4(cv[4]+r1.x, cv[5]+r1.y, cv[6]+r1.z, cv[7]+r1.w);
        } else if (EPI == EPI_BIAS_RELU) {
            float4 b0 = *(const float4*)&bias[c0], b1 = *(const float4*)&bias[c0 + 4];
            float t0 = cv[0]+b0.x, t1 = cv[1]+b0.y, t2 = cv[2]+b0.z, t3 = cv[3]+b0.w;
            float t4 = cv[4]+b1.x, t5 = cv[5]+b1.y, t6 = cv[6]+b1.z, t7 = cv[7]+b1.w;
            float* dst = out + (size_t)r * N + c0;
            *(float4*)dst       = make_float4(fmaxf(t0,0.f), fmaxf(t1,0.f), fmaxf(t2,0.f), fmaxf(t3,0.f));
            *(float4*)(dst + 4) = make_float4(fmaxf(t4,0.f), fmaxf(t5,0.f), fmaxf(t6,0.f), fmaxf(t7,0.f));
        } else { // EPI_BIAS_RES
            float4 b0 = *(const float4*)&bias[c0], b1 = *(const float4*)&bias[c0 + 4];
            const float* rp = res + (size_t)r * N + c0;
            float4 r0 = *(const float4*)rp, r1 = *(const float4*)(rp + 4);
            float* dst = out + (size_t)r * N + c0;
            *(float4*)dst       = make_float4(cv[0]+b0.x+r0.x, cv[1]+b0.y+r0.y, cv[2]+b0.z+r0.z, cv[3]+b0.w+r0.w);
            *(float4*)(dst + 4) = make_float4(cv[4]+b1.x+r1.x, cv[5]+b1.y+r1.y, cv[6]+b1.z+r1.z, cv[7]+b1.w+r1.w);
        }
    }
}

// ---------------- Flash attention (fp32, f32x2, 128q x 128k tiles) ----------------
// 512 threads: thread = 4 query rows (ty 0..31) x 8 key cols (tx 0..15);
// PV: 4 rows x 4 dk (tx*4). 16 warps/SM for latency hiding.
__global__ __launch_bounds__(512, 1)
void attn_kernel(const int* __restrict__ mask)
{
    extern __shared__ float sm[];
    float* Qs = sm;                  // [64][132]  (d-major)
    float* Ks = Qs + 64*132;         // [64][132]  (d-major)
    float* Vs = Ks + 64*132;         // [128][68]  (key-major)
    float* Pr = Vs + 128*68;         // [128][132] (row-major P)

    const int q0 = blockIdx.x * 128;
    const int h  = blockIdx.y;
    const int b  = blockIdx.z;
    const size_t head_off = (((size_t)b * Hn + h) * Sn) * DKn;
    const float* Q = g_q + head_off;
    const float* K = g_k + head_off;
    const float* V = g_v + head_off;

    const int tid = threadIdx.x;
    const int tx = tid & 15, ty = tid >> 4;   // ty 0..31
    const int lr  = tid >> 2;                 // 0..127 loader row
    const int ldc = (tid & 3) * 16;           // 16-d chunk

    // load Q transposed into Qs[d][r]
    {
        const float4* Qg = (const float4*)(Q + (size_t)(q0 + lr) * DKn + ldc);
        #pragma unroll
        for (int c = 0; c < 4; c++) {
            float4 v = Qg[c];
            Qs[(ldc + c*4 + 0)*132 + lr] = v.x;
            Qs[(ldc + c*4 + 1)*132 + lr] = v.y;
            Qs[(ldc + c*4 + 2)*132 + lr] = v.z;
            Qs[(ldc + c*4 + 3)*132 + lr] = v.w;
        }
    }

    u64t o2[4][2];
    float mrun[4], lrun[4];
    #pragma unroll
    for (int i = 0; i < 4; i++) {
        o2[i][0] = 0ull; o2[i][1] = 0ull;
        mrun[i] = -INFINITY; lrun[i] = 0.f;
    }
    __syncthreads();

    for (int k0 = 0; k0 < Sn; k0 += 128) {
        // load K transposed (Ks[d][c]) and V natural (Vs[c][d])
        {
            const float4* Kg = (const float4*)(K + (size_t)(k0 + lr) * DKn + ldc);
            const float4* Vg = (const float4*)(V + (size_t)(k0 + lr) * DKn + ldc);
            #pragma unroll
            for (int c = 0; c < 4; c++) {
                float4 kv = Kg[c];
                Ks[(ldc + c*4 + 0)*132 + lr] = kv.x;
                Ks[(ldc + c*4 + 1)*132 + lr] = kv.y;
                Ks[(ldc + c*4 + 2)*132 + lr] = kv.z;
                Ks[(ldc + c*4 + 3)*132 + lr] = kv.w;
                *(float4*)&Vs[lr*68 + ldc + c*4] = Vg[c];
            }
        }
        __syncthreads();

        // S = Q K^T : s2[4 rows][4 key-pairs]
        u64t s2[4][4];
        #pragma unroll
        for (int i = 0; i < 4; i++)
            #pragma unroll
            for (int jj = 0; jj < 4; jj++) s2[i][jj] = 0ull;

        #pragma unroll 8
        for (int d = 0; d < 64; d++) {
            float4 a4 = *(const float4*)&Qs[d*132 + ty*4];
            ulonglong2 k01 = *(const ulonglong2*)&Ks[d*132 + tx*8];
            ulonglong2 k23 = *(const ulonglong2*)&Ks[d*132 + tx*8 + 4];
            u64t kb[4] = {k01.x, k01.y, k23.x, k23.y};
            float a[4] = {a4.x, a4.y, a4.z, a4.w};
            #pragma unroll
            for (int i = 0; i < 4; i++) {
                u64t ad = pack2(a[i], a[i]);
                #pragma unroll
                for (int jj = 0; jj < 4; jj++)
                    s2[i][jj] = fma2(ad, kb[jj], s2[i][jj]);
            }
        }

        // unpack, scale, mask
        float p[4][8];
        #pragma unroll
        for (int i = 0; i < 4; i++)
            #pragma unroll
            for (int jj = 0; jj < 4; jj++)
                unpack2(s2[i][jj], p[i][2*jj], p[i][2*jj+1]);

        int mv[8];
        #pragma unroll
        for (int j = 0; j < 8; j++) mv[j] = mask[b * Sn + k0 + tx*8 + j];
        #pragma unroll
        for (int i = 0; i < 4; i++)
            #pragma unroll
            for (int j = 0; j < 8; j++) {
                float v = p[i][j] * 0.125f;
                p[i][j] = (mv[j] == 0) ? -1e9f : v;
            }

        // online softmax: each row lives in 16 tx-lanes (same ty)
        #pragma unroll
        for (int i = 0; i < 4; i++) {
            float mx = p[i][0];
            #pragma unroll
            for (int j = 1; j < 8; j++) mx = fmaxf(mx, p[i][j]);
            #pragma unroll
            for (int off = 8; off; off >>= 1)
                mx = fmaxf(mx, __shfl_xor_sync(0xffffffffu, mx, off));
            const float mnew = fmaxf(mrun[i], mx);
            const float al = __expf(mrun[i] - mnew);
            mrun[i] = mnew;
            float sum = 0.f;
            #pragma unroll
            for (int j = 0; j < 8; j++) {
                p[i][j] = __expf(p[i][j] - mnew);
                sum += p[i][j];
            }
            #pragma unroll
            for (int off = 8; off; off >>= 1)
                sum += __shfl_xor_sync(0xffffffffu, sum, off);
            lrun[i] = lrun[i] * al + sum;
            const u64t alp = pack2(al, al);
            o2[i][0] = mul2(alp, o2[i][0]);
            o2[i][1] = mul2(alp, o2[i][1]);
        }

        // store P row-major
        #pragma unroll
        for (int i = 0; i < 4; i++) {
            float* pd = &Pr[(ty*4 + i)*132 + tx*8];
            *(float4*)pd       = make_float4(p[i][0], p[i][1], p[i][2], p[i][3]);
            *(float4*)(pd + 4) = make_float4(p[i][4], p[i][5], p[i][6], p[i][7]);
        }
        __syncthreads();

        // O += P V  (4 rows x 4 dk), P loaded as float4 per 4 keys
        #pragma unroll 2
        for (int kk0 = 0; kk0 < 128; kk0 += 4) {
            float4 pv[4];
            #pragma unroll
            for (int i = 0; i < 4; i++)
                pv[i] = *(const float4*)&Pr[(ty*4 + i)*132 + kk0];
            #pragma unroll
            for (int kkl = 0; kkl < 4; kkl++) {
                ulonglong2 v2 = *(const ulonglong2*)&Vs[(kk0 + kkl)*68 + tx*4];
                #pragma unroll
                for (int i = 0; i < 4; i++) {
                    const float pe = ((const float*)&pv[i])[kkl];
                    const u64t pd = pack2(pe, pe);
                    o2[i][0] = fma2(pd, v2.x, o2[i][0]);
                    o2[i][1] = fma2(pd, v2.y, o2[i][1]);
                }
            }
        }
        __syncthreads();
    }

    // write ctx[b, s, h*64 + dk]
    #pragma unroll
    for (int i = 0; i < 4; i++) {
        const float inv = 1.f / lrun[i];
        float ov[4];
        unpack2(o2[i][0], ov[0], ov[1]);
        unpack2(o2[i][1], ov[2], ov[3]);
        const int r = q0 + ty*4 + i;
        float* dst = g_ctx + ((size_t)b * Sn + r) * Dn + h * DKn + tx*4;
        *(float4*)dst = make_float4(ov[0]*inv, ov[1]*inv, ov[2]*inv, ov[3]*inv);
    }
}

// ---------------- LayerNorm over D=512 ----------------
__global__ __launch_bounds__(256)
void ln_kernel(const float* __restrict__ in, const float* __restrict__ g,
               const float* __restrict__ beta, float* __restrict__ out)
{
    const int row = blockIdx.x;
    const float* x = in + (size_t)row * Dn;
    const int tid = threadIdx.x;

    float v0 = x[tid], v1 = x[tid + 256];
    float s = v0 + v1;
    __shared__ float red[8];
    __shared__ float mu_s, rs_s;
    #pragma unroll
    for (int o = 16; o; o >>= 1) s += __shfl_xor_sync(0xffffffffu, s, o);
    if ((tid & 31) == 0) red[tid >> 5] = s;
    __syncthreads();
    if (tid == 0) {
        float t = 0.f;
        #pragma unroll
        for (int i = 0; i < 8; i++) t += red[i];
        mu_s = t * (1.0f / Dn);
    }
    __syncthreads();
    const float mu = mu_s;
    const float d0 = v0 - mu, d1 = v1 - mu;
    float vs = d0*d0 + d1*d1;
    #pragma unroll
    for (int o = 16; o; o >>= 1) vs += __shfl_xor_sync(0xffffffffu, vs, o);
    if ((tid & 31) == 0) red[tid >> 5] = vs;
    __syncthreads();
    if (tid == 0) {
        float t = 0.f;
        #pragma unroll
        for (int i = 0; i < 8; i++) t += red[i];
        rs_s = rsqrtf(t * (1.0f / Dn) + 1e-5f);
    }
    __syncthreads();
    const float rs = rs_s;
    out[(size_t)row * Dn + tid]       = d0 * rs * g[tid]       + beta[tid];
    out[(size_t)row * Dn + tid + 256] = d1 * rs * g[tid + 256] + beta[tid + 256];
}

// ---------------- launch ----------------
extern "C" void kernel_launch(void* const* d_in, const int* in_sizes, int n_in,
                              void* d_out, int out_size)
{
    const float* x   = (const float*)d_in[0];
    const int*   msk = (const int*)  d_in[1];
    const float* wq  = (const float*)d_in[2];
    const float* wk  = (const float*)d_in[3];
    const float* wv  = (const float*)d_in[4];
    const float* wo  = (const float*)d_in[5];
    const float* w1  = (const float*)d_in[6];
    const float* b1  = (const float*)d_in[7];
    const float* w2  = (const float*)d_in[8];
    const float* b2  = (const float*)d_in[9];
    const float* g1  = (const float*)d_in[10];
    const float* be1 = (const float*)d_in[11];
    const float* g2  = (const float*)d_in[12];
    const float* be2 = (const float*)d_in[13];
    float* out = (float*)d_out;

    float *q, *k, *v, *ctx, *res1, *x1, *ff;
    cudaGetSymbolAddress((void**)&q,    g_q);
    cudaGetSymbolAddress((void**)&k,    g_k);
    cudaGetSymbolAddress((void**)&v,    g_v);
    cudaGetSymbolAddress((void**)&ctx,  g_ctx);
    cudaGetSymbolAddress((void**)&res1, g_res1);
    cudaGetSymbolAddress((void**)&x1,   g_x1);
    cudaGetSymbolAddress((void**)&ff,   g_ff);

    // one-time (idempotent) attribute setup for large smem
    cudaFuncSetAttribute(gemm_kernel<Dn, Dn, EPI_QKV>,
                         cudaFuncAttributeMaxDynamicSharedMemorySize, GEMM_SMEM);
    cudaFuncSetAttribute(gemm_kernel<Dn, Dn, EPI_RES>,
                         cudaFuncAttributeMaxDynamicSharedMemorySize, GEMM_SMEM);
    cudaFuncSetAttribute(gemm_kernel<DFFn, Dn, EPI_BIAS_RELU>,
                         cudaFuncAttributeMaxDynamicSharedMemorySize, GEMM_SMEM);
    cudaFuncSetAttribute(gemm_kernel<Dn, DFFn, EPI_BIAS_RES>,
                         cudaFuncAttributeMaxDynamicSharedMemorySize, GEMM_SMEM);

    const dim3 blk(256);
    const dim3 g512(Dn/128,  Mrows/128);   // (4,64)
    const dim3 gff1(DFFn/128, Mrows/128);  // (16,64)

    // QKV projections -> [B,H,S,DK]
    gemm_kernel<Dn, Dn, EPI_QKV><<<g512, blk, GEMM_SMEM>>>(x, wq, nullptr, nullptr, q);
    gemm_kernel<Dn, Dn, EPI_QKV><<<g512, blk, GEMM_SMEM>>>(x, wk, nullptr, nullptr, k);
    gemm_kernel<Dn, Dn, EPI_QKV><<<g512, blk, GEMM_SMEM>>>(x, wv, nullptr, nullptr, v);

    // attention
    const int smem = (64*132 + 64*132 + 128*68 + 128*132) * (int)sizeof(float); // 169984
    cudaFuncSetAttribute(attn_kernel, cudaFuncAttributeMaxDynamicSharedMemorySize, smem);
    attn_kernel<<<dim3(Sn/128, Hn, Bn), dim3(512), smem>>>(msk);

    // attn_out projection + residual
    gemm_kernel<Dn, Dn, EPI_RES><<<g512, blk, GEMM_SMEM>>>(ctx, wo, nullptr, x, res1);
    // LN1
    ln_kernel<<<Mrows, blk>>>(res1, g1, be1, x1);
    // FFN
    gemm_kernel<DFFn, Dn, EPI_BIAS_RELU><<<gff1, blk, GEMM_SMEM>>>(x1, w1, b1, nullptr, ff);
    gemm_kernel<Dn, DFFn, EPI_BIAS_RES><<<g512, blk, GEMM_SMEM>>>(ff, w2, b2, x1, res1);
    // LN2 -> out
    ln_kernel<<<Mrows, blk>>>(res1, g2, be2, out);
}

// round 7
// speedup vs baseline: 1.1659x; 1.1659x over previous
#include <cuda_runtime.h>
#include <math.h>
#include <stdint.h>

#define Bn   2
#define Sn   4096
#define Dn   512
#define Hn   8
#define DKn  64
#define DFFn 2048
#define Mrows (Bn*Sn)   /* 8192 */

// ---------------- scratch (no allocs allowed) ----------------
__device__ float g_q[Bn*Hn*Sn*DKn];     // [B,H,S,DK]
__device__ float g_k[Bn*Hn*Sn*DKn];
__device__ float g_v[Bn*Hn*Sn*DKn];
__device__ float g_ctx[Mrows*Dn];       // [B,S,D]
__device__ float g_res1[Mrows*Dn];
__device__ float g_x1[Mrows*Dn];
__device__ float g_ff[Mrows*DFFn];

// ---------------- packed f32x2 helpers ----------------
typedef unsigned long long u64t;

__device__ __forceinline__ u64t pack2(float lo, float hi) {
    u64t r;
    asm("mov.b64 %0, {%1, %2};" : "=l"(r) : "f"(lo), "f"(hi));
    return r;
}
__device__ __forceinline__ void unpack2(u64t v, float& lo, float& hi) {
    asm("mov.b64 {%0, %1}, %2;" : "=f"(lo), "=f"(hi) : "l"(v));
}
__device__ __forceinline__ u64t fma2(u64t a, u64t b, u64t c) {
    u64t d;
    asm("fma.rn.f32x2 %0, %1, %2, %3;" : "=l"(d) : "l"(a), "l"(b), "l"(c));
    return d;
}
__device__ __forceinline__ u64t mul2(u64t a, u64t b) {
    u64t d;
    asm("mul.rn.f32x2 %0, %1, %2;" : "=l"(d) : "l"(a), "l"(b));
    return d;
}

// ---------------- GEMM: C[M,N] = A[M,K] @ W[K,N] + epilogue ----------------
// 128x128 block tile, BK=32, 256 threads, 8x8 microtile, f32x2 packed FMA.
// (R4 known-good version: static smem, single buffer.)
#define EPI_QKV       0
#define EPI_RES       1
#define EPI_BIAS_RELU 2
#define EPI_BIAS_RES  3

template<int N, int K, int EPI>
__global__ __launch_bounds__(256, 2)
void gemm_kernel(const float* __restrict__ A, const float* __restrict__ W,
                 const float* __restrict__ bias, const float* __restrict__ res,
                 float* __restrict__ out)
{
    __shared__ float As[32][132];   // k-major A tile
    __shared__ float Bs[32][132];
    const int tid = threadIdx.x;
    const int tx = tid & 15, ty = tid >> 4;
    const int row0 = blockIdx.y * 128;
    const int col0 = blockIdx.x * 128;

    const int ar  = tid >> 1;
    const int akc = (tid & 1) * 16;
    const int bkk = tid >> 3;
    const int bnc = (tid & 7) * 16;

    u64t acc2[8][4];
    #pragma unroll
    for (int i = 0; i < 8; i++)
        #pragma unroll
        for (int jj = 0; jj < 4; jj++) acc2[i][jj] = 0ull;

    for (int k0 = 0; k0 < K; k0 += 32) {
        const float4* Ag = (const float4*)(A + (size_t)(row0 + ar) * K + k0 + akc);
        #pragma unroll
        for (int c = 0; c < 4; c++) {
            float4 v = Ag[c];
            As[akc + c*4 + 0][ar] = v.x;
            As[akc + c*4 + 1][ar] = v.y;
            As[akc + c*4 + 2][ar] = v.z;
            As[akc + c*4 + 3][ar] = v.w;
        }
        const float4* Bg = (const float4*)(W + (size_t)(k0 + bkk) * N + col0 + bnc);
        #pragma unroll
        for (int c = 0; c < 4; c++)
            *(float4*)&Bs[bkk][bnc + c*4] = Bg[c];
        __syncthreads();

        #pragma unroll 8
        for (int kk = 0; kk < 32; kk++) {
            float a[8];
            *(float4*)&a[0] = *(const float4*)&As[kk][ty*8];
            *(float4*)&a[4] = *(const float4*)&As[kk][ty*8 + 4];
            ulonglong2 b01 = *(const ulonglong2*)&Bs[kk][tx*8];
            ulonglong2 b23 = *(const ulonglong2*)&Bs[kk][tx*8 + 4];
            u64t bb[4] = {b01.x, b01.y, b23.x, b23.y};
            #pragma unroll
            for (int i = 0; i < 8; i++) {
                u64t ad = pack2(a[i], a[i]);
                #pragma unroll
                for (int jj = 0; jj < 4; jj++)
                    acc2[i][jj] = fma2(ad, bb[jj], acc2[i][jj]);
            }
        }
        __syncthreads();
    }

    #pragma unroll
    for (int i = 0; i < 8; i++) {
        const int r  = row0 + ty*8 + i;
        const int c0 = col0 + tx*8;
        float cv[8];
        #pragma unroll
        for (int jj = 0; jj < 4; jj++) unpack2(acc2[i][jj], cv[2*jj], cv[2*jj+1]);

        if (EPI == EPI_QKV) {
            const int b = r >> 12, s = r & (Sn - 1);
            const int h = c0 >> 6, dk = c0 & 63;
            float* dst = out + (((size_t)b * Hn + h) * Sn + s) * DKn + dk;
            *(float4*)dst       = make_float4(cv[0], cv[1], cv[2], cv[3]);
            *(float4*)(dst + 4) = make_float4(cv[4], cv[5], cv[6], cv[7]);
        } else if (EPI == EPI_RES) {
            const float* rp = res + (size_t)r * N + c0;
            float4 r0 = *(const float4*)rp, r1 = *(const float4*)(rp + 4);
            float* dst = out + (size_t)r * N + c0;
            *(float4*)dst       = make_float4(cv[0]+r0.x, cv[1]+r0.y, cv[2]+r0.z, cv[3]+r0.w);
            *(float4*)(dst + 4) = make_float4(cv[4]+r1.x, cv[5]+r1.y, cv[6]+r1.z, cv[7]+r1.w);
        } else if (EPI == EPI_BIAS_RELU) {
            float4 b0 = *(const float4*)&bias[c0], b1 = *(const float4*)&bias[c0 + 4];
            float t0 = cv[0]+b0.x, t1 = cv[1]+b0.y, t2 = cv[2]+b0.z, t3 = cv[3]+b0.w;
            float t4 = cv[4]+b1.x, t5 = cv[5]+b1.y, t6 = cv[6]+b1.z, t7 = cv[7]+b1.w;
            float* dst = out + (size_t)r * N + c0;
            *(float4*)dst       = make_float4(fmaxf(t0,0.f), fmaxf(t1,0.f), fmaxf(t2,0.f), fmaxf(t3,0.f));
            *(float4*)(dst + 4) = make_float4(fmaxf(t4,0.f), fmaxf(t5,0.f), fmaxf(t6,0.f), fmaxf(t7,0.f));
        } else { // EPI_BIAS_RES
            float4 b0 = *(const float4*)&bias[c0], b1 = *(const float4*)&bias[c0 + 4];
            const float* rp = res + (size_t)r * N + c0;
            float4 r0 = *(const float4*)rp, r1 = *(const float4*)(rp + 4);
            float* dst = out + (size_t)r * N + c0;
            *(float4*)dst       = make_float4(cv[0]+b0.x+r0.x, cv[1]+b0.y+r0.y, cv[2]+b0.z+r0.z, cv[3]+b0.w+r0.w);
            *(float4*)(dst + 4) = make_float4(cv[4]+b1.x+r1.x, cv[5]+b1.y+r1.y, cv[6]+b1.z+r1.z, cv[7]+b1.w+r1.w);
        }
    }
}

// ---------------- Flash attention (fp32, f32x2, 128q x 128k tiles) ----------------
// 256 threads, 8x8 QK microtile, 8x4 PV microtile.
// Pipelined: V(t) loads hidden under QK(t); K(t+1) loads hidden under PV(t).
// Double-buffered K smem; 2 block barriers per tile.
__global__ __launch_bounds__(256, 1)
void attn_kernel(const int* __restrict__ mask)
{
    extern __shared__ float sm[];
    float* Qs  = sm;                 // [64][132]  (d-major)
    float* Ks0 = Qs + 64*132;        // [64][132]  (d-major)
    float* Ks1 = Ks0 + 64*132;       // [64][132]
    float* Vs  = Ks1 + 64*132;       // [128][68]  (key-major)
    float* Pr  = Vs + 128*68;        // [128][132] (row-major P)

    const int q0 = blockIdx.x * 128;
    const int h  = blockIdx.y;
    const int b  = blockIdx.z;
    const size_t head_off = (((size_t)b * Hn + h) * Sn) * DKn;
    const float* Q = g_q + head_off;
    const float* K = g_k + head_off;
    const float* V = g_v + head_off;

    const int tid = threadIdx.x;
    const int tx = tid & 15, ty = tid >> 4;
    const int lr  = tid >> 1;            // 0..127 loader row
    const int ldc = (tid & 1) * 32;      // 0 or 32 (loader d-chunk)

    // load Q transposed into Qs[d][r], and prologue K tile 0 into Ks0
    {
        const float4* Qg = (const float4*)(Q + (size_t)(q0 + lr) * DKn + ldc);
        const float4* Kg = (const float4*)(K + (size_t)lr * DKn + ldc);
        #pragma unroll
        for (int c = 0; c < 8; c++) {
            float4 v = Qg[c];
            Qs[(ldc + c*4 + 0)*132 + lr] = v.x;
            Qs[(ldc + c*4 + 1)*132 + lr] = v.y;
            Qs[(ldc + c*4 + 2)*132 + lr] = v.z;
            Qs[(ldc + c*4 + 3)*132 + lr] = v.w;
            float4 kv = Kg[c];
            Ks0[(ldc + c*4 + 0)*132 + lr] = kv.x;
            Ks0[(ldc + c*4 + 1)*132 + lr] = kv.y;
            Ks0[(ldc + c*4 + 2)*132 + lr] = kv.z;
            Ks0[(ldc + c*4 + 3)*132 + lr] = kv.w;
        }
    }

    u64t o2[8][2];
    float mrun[8], lrun[8];
    #pragma unroll
    for (int i = 0; i < 8; i++) {
        o2[i][0] = 0ull; o2[i][1] = 0ull;
        mrun[i] = -INFINITY; lrun[i] = 0.f;
    }
    __syncthreads();

    for (int k0 = 0; k0 < Sn; k0 += 128) {
        const float* KsC = ((k0 >> 7) & 1) ? Ks1 : Ks0;   // current
        float*       KsN = ((k0 >> 7) & 1) ? Ks0 : Ks1;   // next (load target)

        // issue V(t) loads now; they complete under QK compute, drained by MID barrier
        {
            const float4* Vg = (const float4*)(V + (size_t)(k0 + lr) * DKn + ldc);
            #pragma unroll
            for (int c = 0; c < 8; c++)
                *(float4*)&Vs[lr*68 + ldc + c*4] = Vg[c];
        }

        // S = Q K^T : s2[8 rows][4 key-pairs]
        u64t s2[8][4];
        #pragma unroll
        for (int i = 0; i < 8; i++)
            #pragma unroll
            for (int jj = 0; jj < 4; jj++) s2[i][jj] = 0ull;

        #pragma unroll 8
        for (int d = 0; d < 64; d++) {
            float a[8];
            *(float4*)&a[0] = *(const float4*)&Qs[d*132 + ty*8];
            *(float4*)&a[4] = *(const float4*)&Qs[d*132 + ty*8 + 4];
            ulonglong2 k01 = *(const ulonglong2*)&KsC[d*132 + tx*8];
            ulonglong2 k23 = *(const ulonglong2*)&KsC[d*132 + tx*8 + 4];
            u64t kb[4] = {k01.x, k01.y, k23.x, k23.y};
            #pragma unroll
            for (int i = 0; i < 8; i++) {
                u64t ad = pack2(a[i], a[i]);
                #pragma unroll
                for (int jj = 0; jj < 4; jj++)
                    s2[i][jj] = fma2(ad, kb[jj], s2[i][jj]);
            }
        }

        // unpack, scale, mask
        float p[8][8];
        #pragma unroll
        for (int i = 0; i < 8; i++)
            #pragma unroll
            for (int jj = 0; jj < 4; jj++)
                unpack2(s2[i][jj], p[i][2*jj], p[i][2*jj+1]);

        int mv[8];
        #pragma unroll
        for (int j = 0; j < 8; j++) mv[j] = mask[b * Sn + k0 + tx*8 + j];
        #pragma unroll
        for (int i = 0; i < 8; i++)
            #pragma unroll
            for (int j = 0; j < 8; j++) {
                float v = p[i][j] * 0.125f;
                p[i][j] = (mv[j] == 0) ? -1e9f : v;
            }

        // online softmax: each row lives in the 16 tx-lanes of its ty group
        #pragma unroll
        for (int i = 0; i < 8; i++) {
            float mx = p[i][0];
            #pragma unroll
            for (int j = 1; j < 8; j++) mx = fmaxf(mx, p[i][j]);
            #pragma unroll
            for (int off = 8; off; off >>= 1)
                mx = fmaxf(mx, __shfl_xor_sync(0xffffffffu, mx, off));
            const float mnew = fmaxf(mrun[i], mx);
            const float al = __expf(mrun[i] - mnew);
            mrun[i] = mnew;
            float sum = 0.f;
            #pragma unroll
            for (int j = 0; j < 8; j++) {
                p[i][j] = __expf(p[i][j] - mnew);
                sum += p[i][j];
            }
            #pragma unroll
            for (int off = 8; off; off >>= 1)
                sum += __shfl_xor_sync(0xffffffffu, sum, off);
            lrun[i] = lrun[i] * al + sum;
            const u64t alp = pack2(al, al);
            o2[i][0] = mul2(alp, o2[i][0]);
            o2[i][1] = mul2(alp, o2[i][1]);
        }

        // store P row-major
        #pragma unroll
        for (int i = 0; i < 8; i++) {
            float* pd = &Pr[(ty*8 + i)*132 + tx*8];
            *(float4*)pd       = make_float4(p[i][0], p[i][1], p[i][2], p[i][3]);
            *(float4*)(pd + 4) = make_float4(p[i][4], p[i][5], p[i][6], p[i][7]);
        }
        __syncthreads();   // MID: Vs(t) + Pr(t) visible; Ks reads of QK done

        // issue K(t+1) loads now; hidden under PV, drained by END barrier
        {
            const int kn = (k0 + 128 < Sn) ? (k0 + 128) : 0;
            const float4* Kg = (const float4*)(K + (size_t)(kn + lr) * DKn + ldc);
            #pragma unroll
            for (int c = 0; c < 8; c++) {
                float4 kv = Kg[c];
                KsN[(ldc + c*4 + 0)*132 + lr] = kv.x;
                KsN[(ldc + c*4 + 1)*132 + lr] = kv.y;
                KsN[(ldc + c*4 + 2)*132 + lr] = kv.z;
                KsN[(ldc + c*4 + 3)*132 + lr] = kv.w;
            }
        }

        // O += P V  (8 rows x 4 dk), P loaded as float4 per 4 keys
        #pragma unroll 2
        for (int kk0 = 0; kk0 < 128; kk0 += 4) {
            float4 pv[8];
            #pragma unroll
            for (int i = 0; i < 8; i++)
                pv[i] = *(const float4*)&Pr[(ty*8 + i)*132 + kk0];
            #pragma unroll
            for (int kkl = 0; kkl < 4; kkl++) {
                ulonglong2 v2 = *(const ulonglong2*)&Vs[(kk0 + kkl)*68 + tx*4];
                #pragma unroll
                for (int i = 0; i < 8; i++) {
                    const float pe = (kkl == 0) ? pv[i].x : (kkl == 1) ? pv[i].y
                                   : (kkl == 2) ? pv[i].z : pv[i].w;
                    const u64t pd = pack2(pe, pe);
                    o2[i][0] = fma2(pd, v2.x, o2[i][0]);
                    o2[i][1] = fma2(pd, v2.y, o2[i][1]);
                }
            }
        }
        __syncthreads();   // END: PV(t) done -> Vs free; K(t+1) stores drained
    }

    // write ctx[b, s, h*64 + dk]
    #pragma unroll
    for (int i = 0; i < 8; i++) {
        const float inv = 1.f / lrun[i];
        float ov[4];
        unpack2(o2[i][0], ov[0], ov[1]);
        unpack2(o2[i][1], ov[2], ov[3]);
        const int r = q0 + ty*8 + i;
        float* dst = g_ctx + ((size_t)b * Sn + r) * Dn + h * DKn + tx*4;
        *(float4*)dst = make_float4(ov[0]*inv, ov[1]*inv, ov[2]*inv, ov[3]*inv);
    }
}

// ---------------- LayerNorm over D=512 ----------------
__global__ __launch_bounds__(256)
void ln_kernel(const float* __restrict__ in, const float* __restrict__ g,
               const float* __restrict__ beta, float* __restrict__ out)
{
    const int row = blockIdx.x;
    const float* x = in + (size_t)row * Dn;
    const int tid = threadIdx.x;

    float v0 = x[tid], v1 = x[tid + 256];
    float s = v0 + v1;
    __shared__ float red[8];
    __shared__ float mu_s, rs_s;
    #pragma unroll
    for (int o = 16; o; o >>= 1) s += __shfl_xor_sync(0xffffffffu, s, o);
    if ((tid & 31) == 0) red[tid >> 5] = s;
    __syncthreads();
    if (tid == 0) {
        float t = 0.f;
        #pragma unroll
        for (int i = 0; i < 8; i++) t += red[i];
        mu_s = t * (1.0f / Dn);
    }
    __syncthreads();
    const float mu = mu_s;
    const float d0 = v0 - mu, d1 = v1 - mu;
    float vs = d0*d0 + d1*d1;
    #pragma unroll
    for (int o = 16; o; o >>= 1) vs += __shfl_xor_sync(0xffffffffu, vs, o);
    if ((tid & 31) == 0) red[tid >> 5] = vs;
    __syncthreads();
    if (tid == 0) {
        float t = 0.f;
        #pragma unroll
        for (int i = 0; i < 8; i++) t += red[i];
        rs_s = rsqrtf(t * (1.0f / Dn) + 1e-5f);
    }
    __syncthreads();
    const float rs = rs_s;
    out[(size_t)row * Dn + tid]       = d0 * rs * g[tid]       + beta[tid];
    out[(size_t)row * Dn + tid + 256] = d1 * rs * g[tid + 256] + beta[tid + 256];
}

// ---------------- launch ----------------
extern "C" void kernel_launch(void* const* d_in, const int* in_sizes, int n_in,
                              void* d_out, int out_size)
{
    const float* x   = (const float*)d_in[0];
    const int*   msk = (const int*)  d_in[1];
    const float* wq  = (const float*)d_in[2];
    const float* wk  = (const float*)d_in[3];
    const float* wv  = (const float*)d_in[4];
    const float* wo  = (const float*)d_in[5];
    const float* w1  = (const float*)d_in[6];
    const float* b1  = (const float*)d_in[7];
    const float* w2  = (const float*)d_in[8];
    const float* b2  = (const float*)d_in[9];
    const float* g1  = (const float*)d_in[10];
    const float* be1 = (const float*)d_in[11];
    const float* g2  = (const float*)d_in[12];
    const float* be2 = (const float*)d_in[13];
    float* out = (float*)d_out;

    float *q, *k, *v, *ctx, *res1, *x1, *ff;
    cudaGetSymbolAddress((void**)&q,    g_q);
    cudaGetSymbolAddress((void**)&k,    g_k);
    cudaGetSymbolAddress((void**)&v,    g_v);
    cudaGetSymbolAddress((void**)&ctx,  g_ctx);
    cudaGetSymbolAddress((void**)&res1, g_res1);
    cudaGetSymbolAddress((void**)&x1,   g_x1);
    cudaGetSymbolAddress((void**)&ff,   g_ff);

    const dim3 blk(256);
    const dim3 g512(Dn/128,  Mrows/128);   // (4,64)
    const dim3 gff1(DFFn/128, Mrows/128);  // (16,64)

    // QKV projections -> [B,H,S,DK]
    gemm_kernel<Dn, Dn, EPI_QKV><<<g512, blk>>>(x, wq, nullptr, nullptr, q);
    gemm_kernel<Dn, Dn, EPI_QKV><<<g512, blk>>>(x, wk, nullptr, nullptr, k);
    gemm_kernel<Dn, Dn, EPI_QKV><<<g512, blk>>>(x, wv, nullptr, nullptr, v);

    // attention: Qs + 2*Ks + Vs + Pr
    const int smem = (64*132 + 2*64*132 + 128*68 + 128*132) * (int)sizeof(float); // 203776
    cudaFuncSetAttribute(attn_kernel, cudaFuncAttributeMaxDynamicSharedMemorySize, smem);
    attn_kernel<<<dim3(Sn/128, Hn, Bn), blk, smem>>>(msk);

    // attn_out projection + residual
    gemm_kernel<Dn, Dn, EPI_RES><<<g512, blk>>>(ctx, wo, nullptr, x, res1);
    // LN1
    ln_kernel<<<Mrows, blk>>>(res1, g1, be1, x1);
    // FFN
    gemm_kernel<DFFn, Dn, EPI_BIAS_RELU><<<gff1, blk>>>(x1, w1, b1, nullptr, ff);
    gemm_kernel<Dn, DFFn, EPI_BIAS_RES><<<g512, blk>>>(ff, w2, b2, x1, res1);
    // LN2 -> out
    ln_kernel<<<Mrows, blk>>>(res1, g2, be2, out);
}

// round 13
// speedup vs baseline: 1.5483x; 1.3280x over previous
#include <cuda_runtime.h>
#include <cuda_bf16.h>
#include <math.h>
#include <stdint.h>

#define Bn   2
#define Sn   4096
#define Dn   512
#define Hn   8
#define DKn  64
#define DFFn 2048
#define Mrows (Bn*Sn)   /* 8192 */

// ---------------- scratch (no allocs allowed) ----------------
__device__ float g_q[Bn*Hn*Sn*DKn];     // [B,H,S,DK]
__device__ float g_k[Bn*Hn*Sn*DKn];
__device__ float g_v[Bn*Hn*Sn*DKn];
__device__ float g_ctx[Mrows*Dn];       // [B,S,D]
__device__ float g_res1[Mrows*Dn];
__device__ float g_x1[Mrows*Dn];
__device__ float g_ff[Mrows*DFFn];

// ---------------- packed f32x2 helpers (attention) ----------------
typedef unsigned long long u64t;

__device__ __forceinline__ u64t pack2(float lo, float hi) {
    u64t r;
    asm("mov.b64 %0, {%1, %2};" : "=l"(r) : "f"(lo), "f"(hi));
    return r;
}
__device__ __forceinline__ void unpack2(u64t v, float& lo, float& hi) {
    asm("mov.b64 {%0, %1}, %2;" : "=f"(lo), "=f"(hi) : "l"(v));
}
__device__ __forceinline__ u64t fma2(u64t a, u64t b, u64t c) {
    u64t d;
    asm("fma.rn.f32x2 %0, %1, %2, %3;" : "=l"(d) : "l"(a), "l"(b), "l"(c));
    return d;
}
__device__ __forceinline__ u64t mul2(u64t a, u64t b) {
    u64t d;
    asm("mul.rn.f32x2 %0, %1, %2;" : "=l"(d) : "l"(a), "l"(b));
    return d;
}

// ---------------- HMMA helpers (legacy mma.sync, works on plain sm_103) ----------------
__device__ __forceinline__ uint32_t smem_u32(const void* p) {
    uint32_t a;
    asm("{ .reg .u64 t; cvta.to.shared.u64 t, %1; cvt.u32.u64 %0, t; }" : "=r"(a) : "l"(p));
    return a;
}
#define LDSM_X4(r0, r1, r2, r3, addr) \
    asm volatile("ldmatrix.sync.aligned.m8n8.x4.shared.b16 {%0,%1,%2,%3}, [%4];" \
                 : "=r"(r0), "=r"(r1), "=r"(r2), "=r"(r3) : "r"(addr))
#define MMA_BF16(d, a, b0v, b1v) \
    asm volatile("mma.sync.aligned.m16n8k16.row.col.f32.bf16.bf16.f32 " \
                 "{%0,%1,%2,%3}, {%4,%5,%6,%7}, {%8,%9}, {%0,%1,%2,%3};" \
                 : "+f"((d)[0]), "+f"((d)[1]), "+f"((d)[2]), "+f"((d)[3]) \
                 : "r"((a)[0]), "r"((a)[1]), "r"((a)[2]), "r"((a)[3]), \
                   "r"(b0v), "r"(b1v))

__device__ __forceinline__ uint32_t pack_bf(float a, float b, float& ra, float& rb) {
    __nv_bfloat16 ha = __float2bfloat16(a);
    __nv_bfloat16 hb = __float2bfloat16(b);
    ra = a - __bfloat162float(ha);
    rb = b - __bfloat162float(hb);
    return ((uint32_t)__bfloat16_as_ushort(hb) << 16) | (uint32_t)__bfloat16_as_ushort(ha);
}
__device__ __forceinline__ uint32_t pack_bf_only(float a, float b) {
    __nv_bfloat16 ha = __float2bfloat16(a);
    __nv_bfloat16 hb = __float2bfloat16(b);
    return ((uint32_t)__bfloat16_as_ushort(hb) << 16) | (uint32_t)__bfloat16_as_ushort(ha);
}

// ---------------- HMMA GEMM: C[M,N] = A[M,K] @ W[K,N] + epilogue ----------------
// 128x128 CTA tile, 8 warps (4x2 -> 32x64 per warp), K chunk 64.
// bf16x3 split: Ah*Wh + Ah*Wl + Al*Wh, fp32 accum in registers.
#define EPI_QKV       0
#define EPI_RES       1
#define EPI_BIAS_RELU 2
#define EPI_BIAS_RES  3

#define TSTRIDE 72                       /* bf16 elems per smem row (144B) */
#define TILE_U16 (128 * TSTRIDE)         /* 9216 u16 = 18432 B */
#define HG_SMEM  (4 * TILE_U16 * 2)      /* Ah, Al, Bh, Bl = 73728 B */

template<int N, int K, int EPI>
__global__ __launch_bounds__(256)
void tc_gemm(const float* __restrict__ A, const float* __restrict__ W,
             const float* __restrict__ bias, const float* __restrict__ res,
             float* __restrict__ out)
{
    extern __shared__ uint16_t hsm[];
    uint16_t* sAh = hsm;
    uint16_t* sAl = sAh + TILE_U16;
    uint16_t* sBh = sAl + TILE_U16;
    uint16_t* sBl = sBh + TILE_U16;
    const uint32_t uAh = smem_u32(sAh);
    const uint32_t uAl = smem_u32(sAl);
    const uint32_t uBh = smem_u32(sBh);
    const uint32_t uBl = smem_u32(sBl);

    const int tid  = threadIdx.x;
    const int wid  = tid >> 5;
    const int lane = tid & 31;
    const int wm   = wid >> 1;          // 0..3 (32-row band)
    const int wn   = wid & 1;           // 0..1 (64-col band)
    const int row0 = blockIdx.y * 128;
    const int col0 = blockIdx.x * 128;

    // ldmatrix lane address components
    const int aRow  = (lane & 15);             // rows 0-15 of the 16x16 tile
    const int aColH = (lane >> 4) * 8;         // col half 0/8
    const int bLi   = lane & 7;
    const int bGrp  = lane >> 3;
    const int bKh   = (bGrp & 1) * 8;          // k half
    const int bNad  = (bGrp >> 1) * 8 + bLi;   // n within 16-wide pair

    float acc[2][8][4];
    #pragma unroll
    for (int mt = 0; mt < 2; mt++)
        #pragma unroll
        for (int nt = 0; nt < 8; nt++)
            #pragma unroll
            for (int q = 0; q < 4; q++) acc[mt][nt][q] = 0.f;

    const int NC = K / 64;
    for (int ch = 0; ch < NC; ch++) {
        if (ch) __syncthreads();

        // ---- load + split A chunk: [128 m][64 k] ----
        {
            const float* Ab = A + (size_t)row0 * K + ch * 64;
            #pragma unroll
            for (int p = 0; p < 16; p++) {
                int idx = tid + p * 256;
                int m = idx >> 5, kp = idx & 31;          // kp: k-pair 0..31
                float2 av = *(const float2*)(Ab + (size_t)m * K + 2 * kp);
                float r0, r1;
                uint32_t hi = pack_bf(av.x, av.y, r0, r1);
                *(uint32_t*)&sAh[m * TSTRIDE + 2 * kp] = hi;
                *(uint32_t*)&sAl[m * TSTRIDE + 2 * kp] = pack_bf_only(r0, r1);
            }
        }
        // ---- load + split W chunk transposed: B[n][k] = W[k][n] ----
        {
            const float* Wb = W + (size_t)(ch * 64) * N + col0;
            #pragma unroll
            for (int p = 0; p < 16; p++) {
                int idx = tid + p * 256;
                int n = idx & 127, kp = idx >> 7;         // kp 0..31
                float w0 = Wb[(size_t)(2 * kp) * N + n];
                float w1 = Wb[(size_t)(2 * kp + 1) * N + n];
                float r0, r1;
                uint32_t hi = pack_bf(w0, w1, r0, r1);
                *(uint32_t*)&sBh[n * TSTRIDE + 2 * kp] = hi;
                *(uint32_t*)&sBl[n * TSTRIDE + 2 * kp] = pack_bf_only(r0, r1);
            }
        }
        __syncthreads();

        // ---- compute: 4 k-steps of 16 ----
        #pragma unroll
        for (int k16 = 0; k16 < 4; k16++) {
            const int kb = k16 * 16;
            uint32_t ah[2][4], al[2][4];
            #pragma unroll
            for (int mt = 0; mt < 2; mt++) {
                uint32_t off = (uint32_t)(((wm * 32 + mt * 16 + aRow) * TSTRIDE + kb + aColH) * 2);
                LDSM_X4(ah[mt][0], ah[mt][1], ah[mt][2], ah[mt][3], uAh + off);
                LDSM_X4(al[mt][0], al[mt][1], al[mt][2], al[mt][3], uAl + off);
            }
            #pragma unroll
            for (int np = 0; np < 4; np++) {
                uint32_t off = (uint32_t)(((wn * 64 + np * 16 + bNad) * TSTRIDE + kb + bKh) * 2);
                uint32_t bh0, bh1, bh2, bh3, bl0, bl1, bl2, bl3;
                LDSM_X4(bh0, bh1, bh2, bh3, uBh + off);
                LDSM_X4(bl0, bl1, bl2, bl3, uBl + off);
                #pragma unroll
                for (int mt = 0; mt < 2; mt++) {
                    MMA_BF16(acc[mt][2*np],   ah[mt], bh0, bh1);
                    MMA_BF16(acc[mt][2*np],   ah[mt], bl0, bl1);
                    MMA_BF16(acc[mt][2*np],   al[mt], bh0, bh1);
                    MMA_BF16(acc[mt][2*np+1], ah[mt], bh2, bh3);
                    MMA_BF16(acc[mt][2*np+1], ah[mt], bl2, bl3);
                    MMA_BF16(acc[mt][2*np+1], al[mt], bh2, bh3);
                }
            }
        }
    }

    // ---- epilogue: c frag layout: d0,d1 = (row l/4, col 2(l%4)+{0,1}); d2,d3 = row+8 ----
    #pragma unroll
    for (int mt = 0; mt < 2; mt++) {
        #pragma unroll
        for (int hh = 0; hh < 2; hh++) {
            const int r = row0 + wm * 32 + mt * 16 + (lane >> 2) + hh * 8;
            #pragma unroll
            for (int nt = 0; nt < 8; nt++) {
                const int c = col0 + wn * 64 + nt * 8 + (lane & 3) * 2;
                float d0 = acc[mt][nt][hh * 2 + 0];
                float d1 = acc[mt][nt][hh * 2 + 1];

                if (EPI == EPI_QKV) {
                    const int bb = r >> 12, s = r & (Sn - 1);
                    const int hd = c >> 6, dk = c & 63;
                    float* dst = out + (((size_t)bb * Hn + hd) * Sn + s) * DKn + dk;
                    *(float2*)dst = make_float2(d0, d1);
                } else if (EPI == EPI_RES) {
                    const float* rp = res + (size_t)r * N + c;
                    float2 rv = *(const float2*)rp;
                    *(float2*)(out + (size_t)r * N + c) = make_float2(d0 + rv.x, d1 + rv.y);
                } else if (EPI == EPI_BIAS_RELU) {
                    float2 bv = *(const float2*)(bias + c);
                    float t0 = d0 + bv.x, t1 = d1 + bv.y;
                    *(float2*)(out + (size_t)r * N + c) =
                        make_float2(fmaxf(t0, 0.f), fmaxf(t1, 0.f));
                } else { // EPI_BIAS_RES
                    float2 bv = *(const float2*)(bias + c);
                    float2 rv = *(const float2*)(res + (size_t)r * N + c);
                    *(float2*)(out + (size_t)r * N + c) =
                        make_float2(d0 + bv.x + rv.x, d1 + bv.y + rv.y);
                }
            }
        }
    }
}

// ---------------- Flash attention (fp32, f32x2, 128q x 128k tiles) ----------------
__global__ __launch_bounds__(256, 1)
void attn_kernel(const int* __restrict__ mask)
{
    extern __shared__ float sm[];
    float* Qs  = sm;                 // [64][132]  (d-major)
    float* Ks0 = Qs + 64*132;        // [64][132]  (d-major)
    float* Ks1 = Ks0 + 64*132;       // [64][132]
    float* Vs  = Ks1 + 64*132;       // [128][68]  (key-major)
    float* Pr  = Vs + 128*68;        // [128][132] (row-major P)

    const int q0 = blockIdx.x * 128;
    const int h  = blockIdx.y;
    const int b  = blockIdx.z;
    const size_t head_off = (((size_t)b * Hn + h) * Sn) * DKn;
    const float* Q = g_q + head_off;
    const float* K = g_k + head_off;
    const float* V = g_v + head_off;

    const int tid = threadIdx.x;
    const int tx = tid & 15, ty = tid >> 4;
    const int lr  = tid >> 1;            // 0..127 loader row
    const int ldc = (tid & 1) * 32;      // 0 or 32 (loader d-chunk)

    {
        const float4* Qg = (const float4*)(Q + (size_t)(q0 + lr) * DKn + ldc);
        const float4* Kg = (const float4*)(K + (size_t)lr * DKn + ldc);
        #pragma unroll
        for (int c = 0; c < 8; c++) {
            float4 v = Qg[c];
            Qs[(ldc + c*4 + 0)*132 + lr] = v.x;
            Qs[(ldc + c*4 + 1)*132 + lr] = v.y;
            Qs[(ldc + c*4 + 2)*132 + lr] = v.z;
            Qs[(ldc + c*4 + 3)*132 + lr] = v.w;
            float4 kv = Kg[c];
            Ks0[(ldc + c*4 + 0)*132 + lr] = kv.x;
            Ks0[(ldc + c*4 + 1)*132 + lr] = kv.y;
            Ks0[(ldc + c*4 + 2)*132 + lr] = kv.z;
            Ks0[(ldc + c*4 + 3)*132 + lr] = kv.w;
        }
    }

    u64t o2[8][2];
    float mrun[8], lrun[8];
    #pragma unroll
    for (int i = 0; i < 8; i++) {
        o2[i][0] = 0ull; o2[i][1] = 0ull;
        mrun[i] = -INFINITY; lrun[i] = 0.f;
    }
    __syncthreads();

    for (int k0 = 0; k0 < Sn; k0 += 128) {
        const float* KsC = ((k0 >> 7) & 1) ? Ks1 : Ks0;
        float*       KsN = ((k0 >> 7) & 1) ? Ks0 : Ks1;

        {
            const float4* Vg = (const float4*)(V + (size_t)(k0 + lr) * DKn + ldc);
            #pragma unroll
            for (int c = 0; c < 8; c++)
                *(float4*)&Vs[lr*68 + ldc + c*4] = Vg[c];
        }

        u64t s2[8][4];
        #pragma unroll
        for (int i = 0; i < 8; i++)
            #pragma unroll
            for (int jj = 0; jj < 4; jj++) s2[i][jj] = 0ull;

        #pragma unroll 8
        for (int d = 0; d < 64; d++) {
            float a[8];
            *(float4*)&a[0] = *(const float4*)&Qs[d*132 + ty*8];
            *(float4*)&a[4] = *(const float4*)&Qs[d*132 + ty*8 + 4];
            ulonglong2 k01 = *(const ulonglong2*)&KsC[d*132 + tx*8];
            ulonglong2 k23 = *(const ulonglong2*)&KsC[d*132 + tx*8 + 4];
            u64t kb[4] = {k01.x, k01.y, k23.x, k23.y};
            #pragma unroll
            for (int i = 0; i < 8; i++) {
                u64t ad = pack2(a[i], a[i]);
                #pragma unroll
                for (int jj = 0; jj < 4; jj++)
                    s2[i][jj] = fma2(ad, kb[jj], s2[i][jj]);
            }
        }

        float p[8][8];
        #pragma unroll
        for (int i = 0; i < 8; i++)
            #pragma unroll
            for (int jj = 0; jj < 4; jj++)
                unpack2(s2[i][jj], p[i][2*jj], p[i][2*jj+1]);

        int mv[8];
        #pragma unroll
        for (int j = 0; j < 8; j++) mv[j] = mask[b * Sn + k0 + tx*8 + j];
        #pragma unroll
        for (int i = 0; i < 8; i++)
            #pragma unroll
            for (int j = 0; j < 8; j++) {
                float v = p[i][j] * 0.125f;
                p[i][j] = (mv[j] == 0) ? -1e9f : v;
            }

        #pragma unroll
        for (int i = 0; i < 8; i++) {
            float mx = p[i][0];
            #pragma unroll
            for (int j = 1; j < 8; j++) mx = fmaxf(mx, p[i][j]);
            #pragma unroll
            for (int off = 8; off; off >>= 1)
                mx = fmaxf(mx, __shfl_xor_sync(0xffffffffu, mx, off));
            const float mnew = fmaxf(mrun[i], mx);
            const float al = __expf(mrun[i] - mnew);
            mrun[i] = mnew;
            float sum = 0.f;
            #pragma unroll
            for (int j = 0; j < 8; j++) {
                p[i][j] = __expf(p[i][j] - mnew);
                sum += p[i][j];
            }
            #pragma unroll
            for (int off = 8; off; off >>= 1)
                sum += __shfl_xor_sync(0xffffffffu, sum, off);
            lrun[i] = lrun[i] * al + sum;
            const u64t alp = pack2(al, al);
            o2[i][0] = mul2(alp, o2[i][0]);
            o2[i][1] = mul2(alp, o2[i][1]);
        }

        #pragma unroll
        for (int i = 0; i < 8; i++) {
            float* pd = &Pr[(ty*8 + i)*132 + tx*8];
            *(float4*)pd       = make_float4(p[i][0], p[i][1], p[i][2], p[i][3]);
            *(float4*)(pd + 4) = make_float4(p[i][4], p[i][5], p[i][6], p[i][7]);
        }
        __syncthreads();

        {
            const int kn = (k0 + 128 < Sn) ? (k0 + 128) : 0;
            const float4* Kg = (const float4*)(K + (size_t)(kn + lr) * DKn + ldc);
            #pragma unroll
            for (int c = 0; c < 8; c++) {
                float4 kv = Kg[c];
                KsN[(ldc + c*4 + 0)*132 + lr] = kv.x;
                KsN[(ldc + c*4 + 1)*132 + lr] = kv.y;
                KsN[(ldc + c*4 + 2)*132 + lr] = kv.z;
                KsN[(ldc + c*4 + 3)*132 + lr] = kv.w;
            }
        }

        #pragma unroll 2
        for (int kk0 = 0; kk0 < 128; kk0 += 4) {
            float4 pv[8];
            #pragma unroll
            for (int i = 0; i < 8; i++)
                pv[i] = *(const float4*)&Pr[(ty*8 + i)*132 + kk0];
            #pragma unroll
            for (int kkl = 0; kkl < 4; kkl++) {
                ulonglong2 v2 = *(const ulonglong2*)&Vs[(kk0 + kkl)*68 + tx*4];
                #pragma unroll
                for (int i = 0; i < 8; i++) {
                    const float pe = (kkl == 0) ? pv[i].x : (kkl == 1) ? pv[i].y
                                   : (kkl == 2) ? pv[i].z : pv[i].w;
                    const u64t pd = pack2(pe, pe);
                    o2[i][0] = fma2(pd, v2.x, o2[i][0]);
                    o2[i][1] = fma2(pd, v2.y, o2[i][1]);
                }
            }
        }
        __syncthreads();
    }

    #pragma unroll
    for (int i = 0; i < 8; i++) {
        const float inv = 1.f / lrun[i];
        float ov[4];
        unpack2(o2[i][0], ov[0], ov[1]);
        unpack2(o2[i][1], ov[2], ov[3]);
        const int r = q0 + ty*8 + i;
        float* dst = g_ctx + ((size_t)b * Sn + r) * Dn + h * DKn + tx*4;
        *(float4*)dst = make_float4(ov[0]*inv, ov[1]*inv, ov[2]*inv, ov[3]*inv);
    }
}

// ---------------- LayerNorm over D=512 ----------------
__global__ __launch_bounds__(256)
void ln_kernel(const float* __restrict__ in, const float* __restrict__ g,
               const float* __restrict__ beta, float* __restrict__ out)
{
    const int row = blockIdx.x;
    const float* x = in + (size_t)row * Dn;
    const int tid = threadIdx.x;

    float v0 = x[tid], v1 = x[tid + 256];
    float s = v0 + v1;
    __shared__ float red[8];
    __shared__ float mu_s, rs_s;
    #pragma unroll
    for (int o = 16; o; o >>= 1) s += __shfl_xor_sync(0xffffffffu, s, o);
    if ((tid & 31) == 0) red[tid >> 5] = s;
    __syncthreads();
    if (tid == 0) {
        float t = 0.f;
        #pragma unroll
        for (int i = 0; i < 8; i++) t += red[i];
        mu_s = t * (1.0f / Dn);
    }
    __syncthreads();
    const float mu = mu_s;
    const float d0 = v0 - mu, d1 = v1 - mu;
    float vs = d0*d0 + d1*d1;
    #pragma unroll
    for (int o = 16; o; o >>= 1) vs += __shfl_xor_sync(0xffffffffu, vs, o);
    if ((tid & 31) == 0) red[tid >> 5] = vs;
    __syncthreads();
    if (tid == 0) {
        float t = 0.f;
        #pragma unroll
        for (int i = 0; i < 8; i++) t += red[i];
        rs_s = rsqrtf(t * (1.0f / Dn) + 1e-5f);
    }
    __syncthreads();
    const float rs = rs_s;
    out[(size_t)row * Dn + tid]       = d0 * rs * g[tid]       + beta[tid];
    out[(size_t)row * Dn + tid + 256] = d1 * rs * g[tid + 256] + beta[tid + 256];
}

// ---------------- launch ----------------
extern "C" void kernel_launch(void* const* d_in, const int* in_sizes, int n_in,
                              void* d_out, int out_size)
{
    const float* x   = (const float*)d_in[0];
    const int*   msk = (const int*)  d_in[1];
    const float* wq  = (const float*)d_in[2];
    const float* wk  = (const float*)d_in[3];
    const float* wv  = (const float*)d_in[4];
    const float* wo  = (const float*)d_in[5];
    const float* w1  = (const float*)d_in[6];
    const float* b1  = (const float*)d_in[7];
    const float* w2  = (const float*)d_in[8];
    const float* b2  = (const float*)d_in[9];
    const float* g1  = (const float*)d_in[10];
    const float* be1 = (const float*)d_in[11];
    const float* g2  = (const float*)d_in[12];
    const float* be2 = (const float*)d_in[13];
    float* out = (float*)d_out;

    float *q, *k, *v, *ctx, *res1, *x1, *ff;
    cudaGetSymbolAddress((void**)&q,    g_q);
    cudaGetSymbolAddress((void**)&k,    g_k);
    cudaGetSymbolAddress((void**)&v,    g_v);
    cudaGetSymbolAddress((void**)&ctx,  g_ctx);
    cudaGetSymbolAddress((void**)&res1, g_res1);
    cudaGetSymbolAddress((void**)&x1,   g_x1);
    cudaGetSymbolAddress((void**)&ff,   g_ff);

    cudaFuncSetAttribute(tc_gemm<Dn, Dn, EPI_QKV>,
                         cudaFuncAttributeMaxDynamicSharedMemorySize, HG_SMEM);
    cudaFuncSetAttribute(tc_gemm<Dn, Dn, EPI_RES>,
                         cudaFuncAttributeMaxDynamicSharedMemorySize, HG_SMEM);
    cudaFuncSetAttribute(tc_gemm<DFFn, Dn, EPI_BIAS_RELU>,
                         cudaFuncAttributeMaxDynamicSharedMemorySize, HG_SMEM);
    cudaFuncSetAttribute(tc_gemm<Dn, DFFn, EPI_BIAS_RES>,
                         cudaFuncAttributeMaxDynamicSharedMemorySize, HG_SMEM);

    const dim3 blk(256);
    const dim3 g512(Dn/128,  Mrows/128);   // (4,64)
    const dim3 gff1(DFFn/128, Mrows/128);  // (16,64)

    // QKV projections -> [B,H,S,DK]
    tc_gemm<Dn, Dn, EPI_QKV><<<g512, blk, HG_SMEM>>>(x, wq, nullptr, nullptr, q);
    tc_gemm<Dn, Dn, EPI_QKV><<<g512, blk, HG_SMEM>>>(x, wk, nullptr, nullptr, k);
    tc_gemm<Dn, Dn, EPI_QKV><<<g512, blk, HG_SMEM>>>(x, wv, nullptr, nullptr, v);

    // attention
    const int smem = (64*132 + 2*64*132 + 128*68 + 128*132) * (int)sizeof(float); // 203776
    cudaFuncSetAttribute(attn_kernel, cudaFuncAttributeMaxDynamicSharedMemorySize, smem);
    attn_kernel<<<dim3(Sn/128, Hn, Bn), blk, smem>>>(msk);

    // attn_out projection + residual
    tc_gemm<Dn, Dn, EPI_RES><<<g512, blk, HG_SMEM>>>(ctx, wo, nullptr, x, res1);
    // LN1
    ln_kernel<<<Mrows, blk>>>(res1, g1, be1, x1);
    // FFN
    tc_gemm<DFFn, Dn, EPI_BIAS_RELU><<<gff1, blk, HG_SMEM>>>(x1, w1, b1, nullptr, ff);
    tc_gemm<Dn, DFFn, EPI_BIAS_RES><<<g512, blk, HG_SMEM>>>(ff, w2, b2, x1, res1);
    // LN2 -> out
    ln_kernel<<<Mrows, blk>>>(res1, g2, be2, out);
}

// round 16
// speedup vs baseline: 2.5384x; 1.6395x over previous
#include <cuda_runtime.h>
#include <cuda_bf16.h>
#include <math.h>
#include <stdint.h>

#define Bn   2
#define Sn   4096
#define Dn   512
#define Hn   8
#define DKn  64
#define DFFn 2048
#define Mrows (Bn*Sn)   /* 8192 */

// ---------------- scratch (no allocs allowed) ----------------
__device__ float g_q[Bn*Hn*Sn*DKn];     // [B,H,S,DK]
__device__ float g_k[Bn*Hn*Sn*DKn];
__device__ float g_v[Bn*Hn*Sn*DKn];
__device__ float g_ctx[Mrows*Dn];       // [B,S,D]
__device__ float g_res1[Mrows*Dn];
__device__ float g_x1[Mrows*Dn];
__device__ float g_ff[Mrows*DFFn];

// ---------------- HMMA helpers (legacy mma.sync, works on plain sm_103) ----------------
__device__ __forceinline__ uint32_t smem_u32(const void* p) {
    uint32_t a;
    asm("{ .reg .u64 t; cvta.to.shared.u64 t, %1; cvt.u32.u64 %0, t; }" : "=r"(a) : "l"(p));
    return a;
}
#define LDSM_X4(r0, r1, r2, r3, addr) \
    asm volatile("ldmatrix.sync.aligned.m8n8.x4.shared.b16 {%0,%1,%2,%3}, [%4];" \
                 : "=r"(r0), "=r"(r1), "=r"(r2), "=r"(r3) : "r"(addr))
#define MMA_BF16(d, a, b0v, b1v) \
    asm volatile("mma.sync.aligned.m16n8k16.row.col.f32.bf16.bf16.f32 " \
                 "{%0,%1,%2,%3}, {%4,%5,%6,%7}, {%8,%9}, {%0,%1,%2,%3};" \
                 : "+f"((d)[0]), "+f"((d)[1]), "+f"((d)[2]), "+f"((d)[3]) \
                 : "r"((a)[0]), "r"((a)[1]), "r"((a)[2]), "r"((a)[3]), \
                   "r"(b0v), "r"(b1v))

__device__ __forceinline__ uint32_t pack_bf(float a, float b, float& ra, float& rb) {
    __nv_bfloat16 ha = __float2bfloat16(a);
    __nv_bfloat16 hb = __float2bfloat16(b);
    ra = a - __bfloat162float(ha);
    rb = b - __bfloat162float(hb);
    return ((uint32_t)__bfloat16_as_ushort(hb) << 16) | (uint32_t)__bfloat16_as_ushort(ha);
}
__device__ __forceinline__ uint32_t pack_bf_only(float a, float b) {
    __nv_bfloat16 ha = __float2bfloat16(a);
    __nv_bfloat16 hb = __float2bfloat16(b);
    return ((uint32_t)__bfloat16_as_ushort(hb) << 16) | (uint32_t)__bfloat16_as_ushort(ha);
}
__device__ __forceinline__ uint16_t bf_hi(float a, float& res) {
    __nv_bfloat16 ha = __float2bfloat16(a);
    res = a - __bfloat162float(ha);
    return __bfloat16_as_ushort(ha);
}

// ---------------- HMMA GEMM: C[M,N] = A[M,K] @ W[K,N] + epilogue ----------------
#define EPI_QKV       0
#define EPI_RES       1
#define EPI_BIAS_RELU 2
#define EPI_BIAS_RES  3

#define TSTRIDE 72                       /* bf16 elems per smem row (144B) */
#define TILE_U16 (128 * TSTRIDE)
#define HG_SMEM  (4 * TILE_U16 * 2)      /* 73728 B */

template<int N, int K, int EPI>
__global__ __launch_bounds__(256)
void tc_gemm(const float* __restrict__ A, const float* __restrict__ W,
             const float* __restrict__ bias, const float* __restrict__ res,
             float* __restrict__ out)
{
    extern __shared__ uint16_t hsm[];
    uint16_t* sAh = hsm;
    uint16_t* sAl = sAh + TILE_U16;
    uint16_t* sBh = sAl + TILE_U16;
    uint16_t* sBl = sBh + TILE_U16;
    const uint32_t uAh = smem_u32(sAh);
    const uint32_t uAl = smem_u32(sAl);
    const uint32_t uBh = smem_u32(sBh);
    const uint32_t uBl = smem_u32(sBl);

    const int tid  = threadIdx.x;
    const int wid  = tid >> 5;
    const int lane = tid & 31;
    const int wm   = wid >> 1;
    const int wn   = wid & 1;
    const int row0 = blockIdx.y * 128;
    const int col0 = blockIdx.x * 128;

    const int aRow  = (lane & 15);
    const int aColH = (lane >> 4) * 8;
    const int bLi   = lane & 7;
    const int bGrp  = lane >> 3;
    const int bKh   = (bGrp & 1) * 8;
    const int bNad  = (bGrp >> 1) * 8 + bLi;

    float acc[2][8][4];
    #pragma unroll
    for (int mt = 0; mt < 2; mt++)
        #pragma unroll
        for (int nt = 0; nt < 8; nt++)
            #pragma unroll
            for (int q = 0; q < 4; q++) acc[mt][nt][q] = 0.f;

    const int NC = K / 64;
    for (int ch = 0; ch < NC; ch++) {
        if (ch) __syncthreads();
        {
            const float* Ab = A + (size_t)row0 * K + ch * 64;
            #pragma unroll
            for (int p = 0; p < 16; p++) {
                int idx = tid + p * 256;
                int m = idx >> 5, kp = idx & 31;
                float2 av = *(const float2*)(Ab + (size_t)m * K + 2 * kp);
                float r0, r1;
                uint32_t hi = pack_bf(av.x, av.y, r0, r1);
                *(uint32_t*)&sAh[m * TSTRIDE + 2 * kp] = hi;
                *(uint32_t*)&sAl[m * TSTRIDE + 2 * kp] = pack_bf_only(r0, r1);
            }
        }
        {
            const float* Wb = W + (size_t)(ch * 64) * N + col0;
            #pragma unroll
            for (int p = 0; p < 16; p++) {
                int idx = tid + p * 256;
                int n = idx & 127, kp = idx >> 7;
                float w0 = Wb[(size_t)(2 * kp) * N + n];
                float w1 = Wb[(size_t)(2 * kp + 1) * N + n];
                float r0, r1;
                uint32_t hi = pack_bf(w0, w1, r0, r1);
                *(uint32_t*)&sBh[n * TSTRIDE + 2 * kp] = hi;
                *(uint32_t*)&sBl[n * TSTRIDE + 2 * kp] = pack_bf_only(r0, r1);
            }
        }
        __syncthreads();

        #pragma unroll
        for (int k16 = 0; k16 < 4; k16++) {
            const int kb = k16 * 16;
            uint32_t ah[2][4], al[2][4];
            #pragma unroll
            for (int mt = 0; mt < 2; mt++) {
                uint32_t off = (uint32_t)(((wm * 32 + mt * 16 + aRow) * TSTRIDE + kb + aColH) * 2);
                LDSM_X4(ah[mt][0], ah[mt][1], ah[mt][2], ah[mt][3], uAh + off);
                LDSM_X4(al[mt][0], al[mt][1], al[mt][2], al[mt][3], uAl + off);
            }
            #pragma unroll
            for (int np = 0; np < 4; np++) {
                uint32_t off = (uint32_t)(((wn * 64 + np * 16 + bNad) * TSTRIDE + kb + bKh) * 2);
                uint32_t bh0, bh1, bh2, bh3, bl0, bl1, bl2, bl3;
                LDSM_X4(bh0, bh1, bh2, bh3, uBh + off);
                LDSM_X4(bl0, bl1, bl2, bl3, uBl + off);
                #pragma unroll
                for (int mt = 0; mt < 2; mt++) {
                    MMA_BF16(acc[mt][2*np],   ah[mt], bh0, bh1);
                    MMA_BF16(acc[mt][2*np],   ah[mt], bl0, bl1);
                    MMA_BF16(acc[mt][2*np],   al[mt], bh0, bh1);
                    MMA_BF16(acc[mt][2*np+1], ah[mt], bh2, bh3);
                    MMA_BF16(acc[mt][2*np+1], ah[mt], bl2, bl3);
                    MMA_BF16(acc[mt][2*np+1], al[mt], bh2, bh3);
                }
            }
        }
    }

    #pragma unroll
    for (int mt = 0; mt < 2; mt++) {
        #pragma unroll
        for (int hh = 0; hh < 2; hh++) {
            const int r = row0 + wm * 32 + mt * 16 + (lane >> 2) + hh * 8;
            #pragma unroll
            for (int nt = 0; nt < 8; nt++) {
                const int c = col0 + wn * 64 + nt * 8 + (lane & 3) * 2;
                float d0 = acc[mt][nt][hh * 2 + 0];
                float d1 = acc[mt][nt][hh * 2 + 1];

                if (EPI == EPI_QKV) {
                    const int bb = r >> 12, s = r & (Sn - 1);
                    const int hd = c >> 6, dk = c & 63;
                    float* dst = out + (((size_t)bb * Hn + hd) * Sn + s) * DKn + dk;
                    *(float2*)dst = make_float2(d0, d1);
                } else if (EPI == EPI_RES) {
                    float2 rv = *(const float2*)(res + (size_t)r * N + c);
                    *(float2*)(out + (size_t)r * N + c) = make_float2(d0 + rv.x, d1 + rv.y);
                } else if (EPI == EPI_BIAS_RELU) {
                    float2 bv = *(const float2*)(bias + c);
                    *(float2*)(out + (size_t)r * N + c) =
                        make_float2(fmaxf(d0 + bv.x, 0.f), fmaxf(d1 + bv.y, 0.f));
                } else {
                    float2 bv = *(const float2*)(bias + c);
                    float2 rv = *(const float2*)(res + (size_t)r * N + c);
                    *(float2*)(out + (size_t)r * N + c) =
                        make_float2(d0 + bv.x + rv.x, d1 + bv.y + rv.y);
                }
            }
        }
    }
}

// ---------------- HMMA flash attention ----------------
// 256 threads, CTA = 128 q-rows; warp = 16 q-rows x 128 keys. bf16x3 splits.
#define QKS 72     /* Q/K smem stride (bf16) */
#define VST 136    /* Vt smem stride (bf16, 128 keys + pad) */
// smem bytes: Qh 18432 | Ql 18432 | Kh 18432 | Kl 18432 | Vth 17408 | Vtl 17408 | mb 16384
#define ATT_SMEM (18432*4 + 17408*2 + 16384)   /* 124928 */

__global__ __launch_bounds__(256, 1)
void attn_kernel(const int* __restrict__ mask)
{
    extern __shared__ char smc[];
    uint16_t* sQh = (uint16_t*)(smc);
    uint16_t* sQl = (uint16_t*)(smc + 18432);
    uint16_t* sKh = (uint16_t*)(smc + 36864);
    uint16_t* sKl = (uint16_t*)(smc + 55296);
    uint16_t* sVh = (uint16_t*)(smc + 73728);
    uint16_t* sVl = (uint16_t*)(smc + 91136);
    float*    mb  = (float*)   (smc + 108544);
    const uint32_t uQh = smem_u32(sQh), uQl = smem_u32(sQl);
    const uint32_t uKh = smem_u32(sKh), uKl = smem_u32(sKl);
    const uint32_t uVh = smem_u32(sVh), uVl = smem_u32(sVl);

    const int q0 = blockIdx.x * 128;
    const int h  = blockIdx.y;
    const int b  = blockIdx.z;
    const size_t head_off = (((size_t)b * Hn + h) * Sn) * DKn;
    const float* Q = g_q + head_off;
    const float* K = g_k + head_off;
    const float* V = g_v + head_off;

    const int tid  = threadIdx.x;
    const int wid  = tid >> 5;
    const int lane = tid & 31;
    const int wrow = wid * 16;

    const int aRow  = (lane & 15);
    const int aColH = (lane >> 4) * 8;
    const int bLi   = lane & 7;
    const int bGrp  = lane >> 3;
    const int bKh   = (bGrp & 1) * 8;
    const int bNad  = (bGrp >> 1) * 8 + bLi;

    // ---- Q convert (once) + mask bias staging ----
    #pragma unroll
    for (int p = 0; p < 16; p++) {
        int ip = tid + p * 256;
        int row = ip >> 5, dkp = ip & 31;
        float2 qv = *(const float2*)(Q + (size_t)(q0 + row) * DKn + 2 * dkp);
        float r0, r1;
        uint32_t hi = pack_bf(qv.x, qv.y, r0, r1);
        *(uint32_t*)&sQh[row * QKS + 2 * dkp] = hi;
        *(uint32_t*)&sQl[row * QKS + 2 * dkp] = pack_bf_only(r0, r1);
    }
    #pragma unroll
    for (int p = 0; p < 16; p++) {
        int i = tid + p * 256;
        mb[i] = (mask[b * Sn + i] == 0) ? -1e9f : 0.f;
    }
    __syncthreads();

    float oacc[8][4];
    #pragma unroll
    for (int nt = 0; nt < 8; nt++)
        #pragma unroll
        for (int qq = 0; qq < 4; qq++) oacc[nt][qq] = 0.f;
    float mrun0 = -1e30f, mrun1 = -1e30f, lrun0 = 0.f, lrun1 = 0.f;

    for (int k0 = 0; k0 < Sn; k0 += 128) {
        // ---- convert K tile [key][dk] and V tile transposed [dk][key] ----
        {
            const float* Kp = K + (size_t)k0 * DKn;
            #pragma unroll
            for (int p = 0; p < 16; p++) {
                int ip = tid + p * 256;
                int row = ip >> 5, dkp = ip & 31;
                float2 kv = *(const float2*)(Kp + (size_t)row * DKn + 2 * dkp);
                float r0, r1;
                uint32_t hi = pack_bf(kv.x, kv.y, r0, r1);
                *(uint32_t*)&sKh[row * QKS + 2 * dkp] = hi;
                *(uint32_t*)&sKl[row * QKS + 2 * dkp] = pack_bf_only(r0, r1);
            }
            const float* Vp = V + (size_t)k0 * DKn;
            #pragma unroll
            for (int p = 0; p < 16; p++) {
                int ip = tid + p * 256;
                int key = ip & 127, dkp = ip >> 7;
                float2 vv = *(const float2*)(Vp + (size_t)key * DKn + 2 * dkp);
                float r0, r1;
                uint16_t h0 = bf_hi(vv.x, r0);
                uint16_t h1 = bf_hi(vv.y, r1);
                sVh[(2*dkp)   * VST + key] = h0;
                sVh[(2*dkp+1) * VST + key] = h1;
                sVl[(2*dkp)   * VST + key] = __bfloat16_as_ushort(__float2bfloat16(r0));
                sVl[(2*dkp+1) * VST + key] = __bfloat16_as_ushort(__float2bfloat16(r1));
            }
        }
        __syncthreads();

        // ---- S = Q K^T (16 rows x 128 keys per warp) ----
        float sacc[16][4];
        #pragma unroll
        for (int nt = 0; nt < 16; nt++)
            #pragma unroll
            for (int qq = 0; qq < 4; qq++) sacc[nt][qq] = 0.f;

        #pragma unroll
        for (int k16 = 0; k16 < 4; k16++) {
            const int kb = k16 * 16;
            uint32_t ah[4], al[4];
            uint32_t aoff = (uint32_t)(((wrow + aRow) * QKS + kb + aColH) * 2);
            LDSM_X4(ah[0], ah[1], ah[2], ah[3], uQh + aoff);
            LDSM_X4(al[0], al[1], al[2], al[3], uQl + aoff);
            #pragma unroll
            for (int np = 0; np < 8; np++) {
                uint32_t boff = (uint32_t)(((np * 16 + bNad) * QKS + kb + bKh) * 2);
                uint32_t bh0, bh1, bh2, bh3, bl0, bl1, bl2, bl3;
                LDSM_X4(bh0, bh1, bh2, bh3, uKh + boff);
                LDSM_X4(bl0, bl1, bl2, bl3, uKl + boff);
                MMA_BF16(sacc[2*np],   ah, bh0, bh1);
                MMA_BF16(sacc[2*np],   ah, bl0, bl1);
                MMA_BF16(sacc[2*np],   al, bh0, bh1);
                MMA_BF16(sacc[2*np+1], ah, bh2, bh3);
                MMA_BF16(sacc[2*np+1], ah, bl2, bl3);
                MMA_BF16(sacc[2*np+1], al, bh2, bh3);
            }
        }

        // ---- scale + mask bias ----
        #pragma unroll
        for (int nt = 0; nt < 16; nt++) {
            float2 bv = *(const float2*)&mb[k0 + nt * 8 + (lane & 3) * 2];
            sacc[nt][0] = sacc[nt][0] * 0.125f + bv.x;
            sacc[nt][1] = sacc[nt][1] * 0.125f + bv.y;
            sacc[nt][2] = sacc[nt][2] * 0.125f + bv.x;
            sacc[nt][3] = sacc[nt][3] * 0.125f + bv.y;
        }

        // ---- online softmax (rows r0=lane/4, r1=r0+8; 4 lanes share a row) ----
        float mx0 = -1e30f, mx1 = -1e30f;
        #pragma unroll
        for (int nt = 0; nt < 16; nt++) {
            mx0 = fmaxf(mx0, fmaxf(sacc[nt][0], sacc[nt][1]));
            mx1 = fmaxf(mx1, fmaxf(sacc[nt][2], sacc[nt][3]));
        }
        mx0 = fmaxf(mx0, __shfl_xor_sync(0xffffffffu, mx0, 1));
        mx0 = fmaxf(mx0, __shfl_xor_sync(0xffffffffu, mx0, 2));
        mx1 = fmaxf(mx1, __shfl_xor_sync(0xffffffffu, mx1, 1));
        mx1 = fmaxf(mx1, __shfl_xor_sync(0xffffffffu, mx1, 2));
        const float mn0 = fmaxf(mrun0, mx0);
        const float mn1 = fmaxf(mrun1, mx1);
        const float al0 = __expf(mrun0 - mn0);
        const float al1 = __expf(mrun1 - mn1);
        mrun0 = mn0; mrun1 = mn1;

        float sum0 = 0.f, sum1 = 0.f;
        #pragma unroll
        for (int nt = 0; nt < 16; nt++) {
            sacc[nt][0] = __expf(sacc[nt][0] - mn0); sum0 += sacc[nt][0];
            sacc[nt][1] = __expf(sacc[nt][1] - mn0); sum0 += sacc[nt][1];
            sacc[nt][2] = __expf(sacc[nt][2] - mn1); sum1 += sacc[nt][2];
            sacc[nt][3] = __expf(sacc[nt][3] - mn1); sum1 += sacc[nt][3];
        }
        sum0 += __shfl_xor_sync(0xffffffffu, sum0, 1);
        sum0 += __shfl_xor_sync(0xffffffffu, sum0, 2);
        sum1 += __shfl_xor_sync(0xffffffffu, sum1, 1);
        sum1 += __shfl_xor_sync(0xffffffffu, sum1, 2);
        lrun0 = lrun0 * al0 + sum0;
        lrun1 = lrun1 * al1 + sum1;

        #pragma unroll
        for (int nt = 0; nt < 8; nt++) {
            oacc[nt][0] *= al0; oacc[nt][1] *= al0;
            oacc[nt][2] *= al1; oacc[nt][3] *= al1;
        }

        // ---- O += P V : P fragments built in registers from sacc ----
        #pragma unroll
        for (int j = 0; j < 8; j++) {
            uint32_t ph[4], pl[4];
            float ra, rb;
            ph[0] = pack_bf(sacc[2*j][0],   sacc[2*j][1],   ra, rb); pl[0] = pack_bf_only(ra, rb);
            ph[1] = pack_bf(sacc[2*j][2],   sacc[2*j][3],   ra, rb); pl[1] = pack_bf_only(ra, rb);
            ph[2] = pack_bf(sacc[2*j+1][0], sacc[2*j+1][1], ra, rb); pl[2] = pack_bf_only(ra, rb);
            ph[3] = pack_bf(sacc[2*j+1][2], sacc[2*j+1][3], ra, rb); pl[3] = pack_bf_only(ra, rb);
            #pragma unroll
            for (int np = 0; np < 4; np++) {
                uint32_t boff = (uint32_t)(((np * 16 + bNad) * VST + j * 16 + bKh) * 2);
                uint32_t bh0, bh1, bh2, bh3, bl0, bl1, bl2, bl3;
                LDSM_X4(bh0, bh1, bh2, bh3, uVh + boff);
                LDSM_X4(bl0, bl1, bl2, bl3, uVl + boff);
                MMA_BF16(oacc[2*np],   ph, bh0, bh1);
                MMA_BF16(oacc[2*np],   ph, bl0, bl1);
                MMA_BF16(oacc[2*np],   pl, bh0, bh1);
                MMA_BF16(oacc[2*np+1], ph, bh2, bh3);
                MMA_BF16(oacc[2*np+1], ph, bl2, bl3);
                MMA_BF16(oacc[2*np+1], pl, bh2, bh3);
            }
        }
        __syncthreads();
    }

    // ---- write ctx ----
    const float inv0 = 1.f / lrun0;
    const float inv1 = 1.f / lrun1;
    const int r0g = q0 + wrow + (lane >> 2);
    const int r1g = r0g + 8;
    #pragma unroll
    for (int nt = 0; nt < 8; nt++) {
        const int c = h * DKn + nt * 8 + (lane & 3) * 2;
        *(float2*)(g_ctx + ((size_t)b * Sn + r0g) * Dn + c) =
            make_float2(oacc[nt][0] * inv0, oacc[nt][1] * inv0);
        *(float2*)(g_ctx + ((size_t)b * Sn + r1g) * Dn + c) =
            make_float2(oacc[nt][2] * inv1, oacc[nt][3] * inv1);
    }
}

// ---------------- LayerNorm over D=512 ----------------
__global__ __launch_bounds__(256)
void ln_kernel(const float* __restrict__ in, const float* __restrict__ g,
               const float* __restrict__ beta, float* __restrict__ out)
{
    const int row = blockIdx.x;
    const float* x = in + (size_t)row * Dn;
    const int tid = threadIdx.x;

    float v0 = x[tid], v1 = x[tid + 256];
    float s = v0 + v1;
    __shared__ float red[8];
    __shared__ float mu_s, rs_s;
    #pragma unroll
    for (int o = 16; o; o >>= 1) s += __shfl_xor_sync(0xffffffffu, s, o);
    if ((tid & 31) == 0) red[tid >> 5] = s;
    __syncthreads();
    if (tid == 0) {
        float t = 0.f;
        #pragma unroll
        for (int i = 0; i < 8; i++) t += red[i];
        mu_s = t * (1.0f / Dn);
    }
    __syncthreads();
    const float mu = mu_s;
    const float d0 = v0 - mu, d1 = v1 - mu;
    float vs = d0*d0 + d1*d1;
    #pragma unroll
    for (int o = 16; o; o >>= 1) vs += __shfl_xor_sync(0xffffffffu, vs, o);
    if ((tid & 31) == 0) red[tid >> 5] = vs;
    __syncthreads();
    if (tid == 0) {
        float t = 0.f;
        #pragma unroll
        for (int i = 0; i < 8; i++) t += red[i];
        rs_s = rsqrtf(t * (1.0f / Dn) + 1e-5f);
    }
    __syncthreads();
    const float rs = rs_s;
    out[(size_t)row * Dn + tid]       = d0 * rs * g[tid]       + beta[tid];
    out[(size_t)row * Dn + tid + 256] = d1 * rs * g[tid + 256] + beta[tid + 256];
}

// ---------------- launch ----------------
extern "C" void kernel_launch(void* const* d_in, const int* in_sizes, int n_in,
                              void* d_out, int out_size)
{
    const float* x   = (const float*)d_in[0];
    const int*   msk = (const int*)  d_in[1];
    const float* wq  = (const float*)d_in[2];
    const float* wk  = (const float*)d_in[3];
    const float* wv  = (const float*)d_in[4];
    const float* wo  = (const float*)d_in[5];
    const float* w1  = (const float*)d_in[6];
    const float* b1  = (const float*)d_in[7];
    const float* w2  = (const float*)d_in[8];
    const float* b2  = (const float*)d_in[9];
    const float* g1  = (const float*)d_in[10];
    const float* be1 = (const float*)d_in[11];
    const float* g2  = (const float*)d_in[12];
    const float* be2 = (const float*)d_in[13];
    float* out = (float*)d_out;

    float *q, *k, *v, *ctx, *res1, *x1, *ff;
    cudaGetSymbolAddress((void**)&q,    g_q);
    cudaGetSymbolAddress((void**)&k,    g_k);
    cudaGetSymbolAddress((void**)&v,    g_v);
    cudaGetSymbolAddress((void**)&ctx,  g_ctx);
    cudaGetSymbolAddress((void**)&res1, g_res1);
    cudaGetSymbolAddress((void**)&x1,   g_x1);
    cudaGetSymbolAddress((void**)&ff,   g_ff);

    cudaFuncSetAttribute(tc_gemm<Dn, Dn, EPI_QKV>,
                         cudaFuncAttributeMaxDynamicSharedMemorySize, HG_SMEM);
    cudaFuncSetAttribute(tc_gemm<Dn, Dn, EPI_RES>,
                         cudaFuncAttributeMaxDynamicSharedMemorySize, HG_SMEM);
    cudaFuncSetAttribute(tc_gemm<DFFn, Dn, EPI_BIAS_RELU>,
                         cudaFuncAttributeMaxDynamicSharedMemorySize, HG_SMEM);
    cudaFuncSetAttribute(tc_gemm<Dn, DFFn, EPI_BIAS_RES>,
                         cudaFuncAttributeMaxDynamicSharedMemorySize, HG_SMEM);
    cudaFuncSetAttribute(attn_kernel,
                         cudaFuncAttributeMaxDynamicSharedMemorySize, ATT_SMEM);

    const dim3 blk(256);
    const dim3 g512(Dn/128,  Mrows/128);   // (4,64)
    const dim3 gff1(DFFn/128, Mrows/128);  // (16,64)

    // QKV projections -> [B,H,S,DK]
    tc_gemm<Dn, Dn, EPI_QKV><<<g512, blk, HG_SMEM>>>(x, wq, nullptr, nullptr, q);
    tc_gemm<Dn, Dn, EPI_QKV><<<g512, blk, HG_SMEM>>>(x, wk, nullptr, nullptr, k);
    tc_gemm<Dn, Dn, EPI_QKV><<<g512, blk, HG_SMEM>>>(x, wv, nullptr, nullptr, v);

    // attention (HMMA)
    attn_kernel<<<dim3(Sn/128, Hn, Bn), blk, ATT_SMEM>>>(msk);

    // attn_out projection + residual
    tc_gemm<Dn, Dn, EPI_RES><<<g512, blk, HG_SMEM>>>(ctx, wo, nullptr, x, res1);
    // LN1
    ln_kernel<<<Mrows, blk>>>(res1, g1, be1, x1);
    // FFN
    tc_gemm<DFFn, Dn, EPI_BIAS_RELU><<<gff1, blk, HG_SMEM>>>(x1, w1, b1, nullptr, ff);
    tc_gemm<Dn, DFFn, EPI_BIAS_RES><<<g512, blk, HG_SMEM>>>(ff, w2, b2, x1, res1);
    // LN2 -> out
    ln_kernel<<<Mrows, blk>>>(res1, g2, be2, out);
}

// round 17
// speedup vs baseline: 3.2806x; 1.2924x over previous
#include <cuda_runtime.h>
#include <cuda_bf16.h>
#include <math.h>
#include <stdint.h>

#define Bn   2
#define Sn   4096
#define Dn   512
#define Hn   8
#define DKn  64
#define DFFn 2048
#define Mrows (Bn*Sn)   /* 8192 */
#define NQKV (Bn*Hn*Sn*DKn)   /* 4194304 */

// ---------------- scratch (no allocs allowed) ----------------
__device__ uint16_t g_qh[NQKV], g_ql[NQKV];   // [B,H,S,DK] bf16 hi/lo
__device__ uint16_t g_kh[NQKV], g_kl[NQKV];   // [B,H,S,DK]
__device__ uint16_t g_vh[NQKV], g_vl[NQKV];   // [B,H,DK,S] (transposed)
__device__ float g_ctx[Mrows*Dn];             // [B,S,D]
__device__ float g_res1[Mrows*Dn];
__device__ float g_x1[Mrows*Dn];
__device__ float g_ff[Mrows*DFFn];

// ---------------- HMMA helpers (legacy mma.sync, works on plain sm_103) ----------------
__device__ __forceinline__ uint32_t smem_u32(const void* p) {
    uint32_t a;
    asm("{ .reg .u64 t; cvta.to.shared.u64 t, %1; cvt.u32.u64 %0, t; }" : "=r"(a) : "l"(p));
    return a;
}
#define LDSM_X4(r0, r1, r2, r3, addr) \
    asm volatile("ldmatrix.sync.aligned.m8n8.x4.shared.b16 {%0,%1,%2,%3}, [%4];" \
                 : "=r"(r0), "=r"(r1), "=r"(r2), "=r"(r3) : "r"(addr))
#define MMA_BF16(d, a, b0v, b1v) \
    asm volatile("mma.sync.aligned.m16n8k16.row.col.f32.bf16.bf16.f32 " \
                 "{%0,%1,%2,%3}, {%4,%5,%6,%7}, {%8,%9}, {%0,%1,%2,%3};" \
                 : "+f"((d)[0]), "+f"((d)[1]), "+f"((d)[2]), "+f"((d)[3]) \
                 : "r"((a)[0]), "r"((a)[1]), "r"((a)[2]), "r"((a)[3]), \
                   "r"(b0v), "r"(b1v))
#define CP_ASYNC16(sdst, gsrc) \
    asm volatile("cp.async.cg.shared.global [%0], [%1], 16;" \
                 :: "r"(sdst), "l"(__cvta_generic_to_global(gsrc)))
#define CP_COMMIT() asm volatile("cp.async.commit_group;" ::: "memory")
#define CP_WAIT1()  asm volatile("cp.async.wait_group 1;" ::: "memory")
#define CP_WAIT0()  asm volatile("cp.async.wait_group 0;" ::: "memory")

__device__ __forceinline__ uint32_t pack_bf(float a, float b, float& ra, float& rb) {
    __nv_bfloat16 ha = __float2bfloat16(a);
    __nv_bfloat16 hb = __float2bfloat16(b);
    ra = a - __bfloat162float(ha);
    rb = b - __bfloat162float(hb);
    return ((uint32_t)__bfloat16_as_ushort(hb) << 16) | (uint32_t)__bfloat16_as_ushort(ha);
}
__device__ __forceinline__ uint32_t pack_bf_only(float a, float b) {
    __nv_bfloat16 ha = __float2bfloat16(a);
    __nv_bfloat16 hb = __float2bfloat16(b);
    return ((uint32_t)__bfloat16_as_ushort(hb) << 16) | (uint32_t)__bfloat16_as_ushort(ha);
}
__device__ __forceinline__ uint16_t bf_hi(float a, float& res) {
    __nv_bfloat16 ha = __float2bfloat16(a);
    res = a - __bfloat162float(ha);
    return __bfloat16_as_ushort(ha);
}

// ---------------- HMMA GEMM: C[M,N] = A[M,K] @ W[K,N] + epilogue ----------------
#define EPI_QK_HL     0   /* write bf16 hi/lo to oh/ol, [B,H,S,DK] */
#define EPI_RES       1
#define EPI_BIAS_RELU 2
#define EPI_BIAS_RES  3
#define EPI_V_HL      4   /* write bf16 hi/lo to oh/ol, transposed [B,H,DK,S] */

#define TSTRIDE 72                       /* bf16 elems per smem row (144B) */
#define TILE_U16 (128 * TSTRIDE)
#define HG_SMEM  (4 * TILE_U16 * 2)      /* 73728 B */

template<int N, int K, int EPI>
__global__ __launch_bounds__(256)
void tc_gemm(const float* __restrict__ A, const float* __restrict__ W,
             const float* __restrict__ bias, const float* __restrict__ res,
             float* __restrict__ out,
             uint16_t* __restrict__ oh, uint16_t* __restrict__ ol)
{
    extern __shared__ uint16_t hsm[];
    uint16_t* sAh = hsm;
    uint16_t* sAl = sAh + TILE_U16;
    uint16_t* sBh = sAl + TILE_U16;
    uint16_t* sBl = sBh + TILE_U16;
    const uint32_t uAh = smem_u32(sAh);
    const uint32_t uAl = smem_u32(sAl);
    const uint32_t uBh = smem_u32(sBh);
    const uint32_t uBl = smem_u32(sBl);

    const int tid  = threadIdx.x;
    const int wid  = tid >> 5;
    const int lane = tid & 31;
    const int wm   = wid >> 1;
    const int wn   = wid & 1;
    const int row0 = blockIdx.y * 128;
    const int col0 = blockIdx.x * 128;

    const int aRow  = (lane & 15);
    const int aColH = (lane >> 4) * 8;
    const int bLi   = lane & 7;
    const int bGrp  = lane >> 3;
    const int bKh   = (bGrp & 1) * 8;
    const int bNad  = (bGrp >> 1) * 8 + bLi;

    float acc[2][8][4];
    #pragma unroll
    for (int mt = 0; mt < 2; mt++)
        #pragma unroll
        for (int nt = 0; nt < 8; nt++)
            #pragma unroll
            for (int q = 0; q < 4; q++) acc[mt][nt][q] = 0.f;

    const int NC = K / 64;
    for (int ch = 0; ch < NC; ch++) {
        if (ch) __syncthreads();
        {
            const float* Ab = A + (size_t)row0 * K + ch * 64;
            #pragma unroll
            for (int p = 0; p < 16; p++) {
                int idx = tid + p * 256;
                int m = idx >> 5, kp = idx & 31;
                float2 av = *(const float2*)(Ab + (size_t)m * K + 2 * kp);
                float r0, r1;
                uint32_t hi = pack_bf(av.x, av.y, r0, r1);
                *(uint32_t*)&sAh[m * TSTRIDE + 2 * kp] = hi;
                *(uint32_t*)&sAl[m * TSTRIDE + 2 * kp] = pack_bf_only(r0, r1);
            }
        }
        {
            const float* Wb = W + (size_t)(ch * 64) * N + col0;
            #pragma unroll
            for (int p = 0; p < 16; p++) {
                int idx = tid + p * 256;
                int n = idx & 127, kp = idx >> 7;
                float w0 = Wb[(size_t)(2 * kp) * N + n];
                float w1 = Wb[(size_t)(2 * kp + 1) * N + n];
                float r0, r1;
                uint32_t hi = pack_bf(w0, w1, r0, r1);
                *(uint32_t*)&sBh[n * TSTRIDE + 2 * kp] = hi;
                *(uint32_t*)&sBl[n * TSTRIDE + 2 * kp] = pack_bf_only(r0, r1);
            }
        }
        __syncthreads();

        #pragma unroll
        for (int k16 = 0; k16 < 4; k16++) {
            const int kb = k16 * 16;
            uint32_t ah[2][4], al[2][4];
            #pragma unroll
            for (int mt = 0; mt < 2; mt++) {
                uint32_t off = (uint32_t)(((wm * 32 + mt * 16 + aRow) * TSTRIDE + kb + aColH) * 2);
                LDSM_X4(ah[mt][0], ah[mt][1], ah[mt][2], ah[mt][3], uAh + off);
                LDSM_X4(al[mt][0], al[mt][1], al[mt][2], al[mt][3], uAl + off);
            }
            #pragma unroll
            for (int np = 0; np < 4; np++) {
                uint32_t off = (uint32_t)(((wn * 64 + np * 16 + bNad) * TSTRIDE + kb + bKh) * 2);
                uint32_t bh0, bh1, bh2, bh3, bl0, bl1, bl2, bl3;
                LDSM_X4(bh0, bh1, bh2, bh3, uBh + off);
                LDSM_X4(bl0, bl1, bl2, bl3, uBl + off);
                #pragma unroll
                for (int mt = 0; mt < 2; mt++) {
                    MMA_BF16(acc[mt][2*np],   ah[mt], bh0, bh1);
                    MMA_BF16(acc[mt][2*np],   ah[mt], bl0, bl1);
                    MMA_BF16(acc[mt][2*np],   al[mt], bh0, bh1);
                    MMA_BF16(acc[mt][2*np+1], ah[mt], bh2, bh3);
                    MMA_BF16(acc[mt][2*np+1], ah[mt], bl2, bl3);
                    MMA_BF16(acc[mt][2*np+1], al[mt], bh2, bh3);
                }
            }
        }
    }

    #pragma unroll
    for (int mt = 0; mt < 2; mt++) {
        #pragma unroll
        for (int hh = 0; hh < 2; hh++) {
            const int r = row0 + wm * 32 + mt * 16 + (lane >> 2) + hh * 8;
            #pragma unroll
            for (int nt = 0; nt < 8; nt++) {
                const int c = col0 + wn * 64 + nt * 8 + (lane & 3) * 2;
                float d0 = acc[mt][nt][hh * 2 + 0];
                float d1 = acc[mt][nt][hh * 2 + 1];

                if (EPI == EPI_QK_HL) {
                    const int bb = r >> 12, s = r & (Sn - 1);
                    const int hd = c >> 6, dk = c & 63;
                    size_t idx = (((size_t)bb * Hn + hd) * Sn + s) * DKn + dk;
                    float r0, r1;
                    uint32_t hi = pack_bf(d0, d1, r0, r1);
                    *(uint32_t*)&oh[idx] = hi;
                    *(uint32_t*)&ol[idx] = pack_bf_only(r0, r1);
                } else if (EPI == EPI_V_HL) {
                    const int bb = r >> 12, s = r & (Sn - 1);
                    const int hd = c >> 6, dk = c & 63;
                    size_t idxT = (((size_t)bb * Hn + hd) * DKn + dk) * Sn + s;
                    float r0, r1;
                    uint16_t h0 = bf_hi(d0, r0);
                    uint16_t h1 = bf_hi(d1, r1);
                    oh[idxT]      = h0;
                    oh[idxT + Sn] = h1;
                    ol[idxT]      = __bfloat16_as_ushort(__float2bfloat16(r0));
                    ol[idxT + Sn] = __bfloat16_as_ushort(__float2bfloat16(r1));
                } else if (EPI == EPI_RES) {
                    float2 rv = *(const float2*)(res + (size_t)r * N + c);
                    *(float2*)(out + (size_t)r * N + c) = make_float2(d0 + rv.x, d1 + rv.y);
                } else if (EPI == EPI_BIAS_RELU) {
                    float2 bv = *(const float2*)(bias + c);
                    *(float2*)(out + (size_t)r * N + c) =
                        make_float2(fmaxf(d0 + bv.x, 0.f), fmaxf(d1 + bv.y, 0.f));
                } else {
                    float2 bv = *(const float2*)(bias + c);
                    float2 rv = *(const float2*)(res + (size_t)r * N + c);
                    *(float2*)(out + (size_t)r * N + c) =
                        make_float2(d0 + bv.x + rv.x, d1 + bv.y + rv.y);
                }
            }
        }
    }
}

// ---------------- HMMA flash attention, cp.async double-buffered ----------------
// smem layout (bytes):
//   Qh 0 (18432) | Ql 18432 (18432) | mb 36864 (16384) | stages @53248, 2 x 71680:
//     per stage: Kh +0 (18432) | Kl +18432 | Vh +36864 (17408) | Vl +54272
#define QKS 72
#define VST 136
#define STG_SZ   71680
#define STG_BASE 53248
#define ATT_SMEM (STG_BASE + 2*STG_SZ)   /* 196608 */

__global__ __launch_bounds__(256, 1)
void attn_kernel(const int* __restrict__ mask)
{
    extern __shared__ char smc[];
    const uint32_t sb = smem_u32(smc);
    const uint32_t uQh = sb;
    const uint32_t uQl = sb + 18432;
    float* mb = (float*)(smc + 36864);

    const int q0 = blockIdx.x * 128;
    const int h  = blockIdx.y;
    const int b  = blockIdx.z;
    const size_t head   = (((size_t)b * Hn + h) * Sn) * DKn;   // [B,H,S,DK]
    const size_t headT  = (((size_t)b * Hn + h) * DKn) * Sn;   // [B,H,DK,S]
    const uint16_t* Qh = g_qh + head + (size_t)q0 * DKn;
    const uint16_t* Ql = g_ql + head + (size_t)q0 * DKn;
    const uint16_t* Kh = g_kh + head;
    const uint16_t* Kl = g_kl + head;
    const uint16_t* Vh = g_vh + headT;
    const uint16_t* Vl = g_vl + headT;

    const int tid  = threadIdx.x;
    const int wid  = tid >> 5;
    const int lane = tid & 31;
    const int wrow = wid * 16;

    const int aRow  = (lane & 15);
    const int aColH = (lane >> 4) * 8;
    const int bLi   = lane & 7;
    const int bGrp  = lane >> 3;
    const int bKh   = (bGrp & 1) * 8;
    const int bNad  = (bGrp >> 1) * 8 + bLi;

    // ---- async copy helpers (inlined loops) ----
    // QK tile: 128 rows x 64 u16, dst stride QKS
    // V  tile: 64 rows x 128 u16 (keys contiguous), dst stride VST, src row stride Sn

    // prologue: Q (hi+lo) + K/V tile 0 into stage 0, one commit group
    #pragma unroll
    for (int i = 0; i < 4; i++) {
        int c = tid + i * 256;
        int row = c >> 3, col8 = (c & 7) * 8;
        CP_ASYNC16(uQh + (uint32_t)((row * QKS + col8) * 2), Qh + (size_t)row * DKn + col8);
        CP_ASYNC16(uQl + (uint32_t)((row * QKS + col8) * 2), Ql + (size_t)row * DKn + col8);
    }
    {
        const uint32_t s0 = sb + STG_BASE;
        #pragma unroll
        for (int i = 0; i < 4; i++) {
            int c = tid + i * 256;
            int row = c >> 3, col8 = (c & 7) * 8;
            CP_ASYNC16(s0 +         (uint32_t)((row * QKS + col8) * 2), Kh + (size_t)row * DKn + col8);
            CP_ASYNC16(s0 + 18432 + (uint32_t)((row * QKS + col8) * 2), Kl + (size_t)row * DKn + col8);
        }
        #pragma unroll
        for (int i = 0; i < 4; i++) {
            int c = tid + i * 256;
            int row = c >> 4, col8 = (c & 15) * 8;
            CP_ASYNC16(s0 + 36864 + (uint32_t)((row * VST + col8) * 2), Vh + (size_t)row * Sn + col8);
            CP_ASYNC16(s0 + 54272 + (uint32_t)((row * VST + col8) * 2), Vl + (size_t)row * Sn + col8);
        }
    }
    CP_COMMIT();

    // mask bias staging (regular stores, covered by first barrier)
    #pragma unroll
    for (int p = 0; p < 16; p++) {
        int i = tid + p * 256;
        mb[i] = (mask[b * Sn + i] == 0) ? -1e9f : 0.f;
    }

    float oacc[8][4];
    #pragma unroll
    for (int nt = 0; nt < 8; nt++)
        #pragma unroll
        for (int qq = 0; qq < 4; qq++) oacc[nt][qq] = 0.f;
    float mrun0 = -1e30f, mrun1 = -1e30f, lrun0 = 0.f, lrun1 = 0.f;

    const int NT = Sn / 128;
    for (int t = 0; t < NT; t++) {
        const uint32_t stg = sb + STG_BASE + (uint32_t)(t & 1) * STG_SZ;

        if (t + 1 < NT) {
            const uint32_t sn = sb + STG_BASE + (uint32_t)((t + 1) & 1) * STG_SZ;
            const int kn = (t + 1) * 128;
            #pragma unroll
            for (int i = 0; i < 4; i++) {
                int c = tid + i * 256;
                int row = c >> 3, col8 = (c & 7) * 8;
                CP_ASYNC16(sn +         (uint32_t)((row * QKS + col8) * 2),
                           Kh + (size_t)(kn + row) * DKn + col8);
                CP_ASYNC16(sn + 18432 + (uint32_t)((row * QKS + col8) * 2),
                           Kl + (size_t)(kn + row) * DKn + col8);
            }
            #pragma unroll
            for (int i = 0; i < 4; i++) {
                int c = tid + i * 256;
                int row = c >> 4, col8 = (c & 15) * 8;
                CP_ASYNC16(sn + 36864 + (uint32_t)((row * VST + col8) * 2),
                           Vh + (size_t)row * Sn + kn + col8);
                CP_ASYNC16(sn + 54272 + (uint32_t)((row * VST + col8) * 2),
                           Vl + (size_t)row * Sn + kn + col8);
            }
            CP_COMMIT();
            CP_WAIT1();
        } else {
            CP_WAIT0();
        }
        __syncthreads();   // tile t (and Q on t=0) visible to all

        const uint32_t uKh = stg;
        const uint32_t uKl = stg + 18432;
        const uint32_t uVh = stg + 36864;
        const uint32_t uVl = stg + 54272;
        const int k0 = t * 128;

        // ---- S = Q K^T (16 rows x 128 keys per warp) ----
        float sacc[16][4];
        #pragma unroll
        for (int nt = 0; nt < 16; nt++)
            #pragma unroll
            for (int qq = 0; qq < 4; qq++) sacc[nt][qq] = 0.f;

        #pragma unroll
        for (int k16 = 0; k16 < 4; k16++) {
            const int kb = k16 * 16;
            uint32_t ah[4], al[4];
            uint32_t aoff = (uint32_t)(((wrow + aRow) * QKS + kb + aColH) * 2);
            LDSM_X4(ah[0], ah[1], ah[2], ah[3], uQh + aoff);
            LDSM_X4(al[0], al[1], al[2], al[3], uQl + aoff);
            #pragma unroll
            for (int np = 0; np < 8; np++) {
                uint32_t boff = (uint32_t)(((np * 16 + bNad) * QKS + kb + bKh) * 2);
                uint32_t bh0, bh1, bh2, bh3, bl0, bl1, bl2, bl3;
                LDSM_X4(bh0, bh1, bh2, bh3, uKh + boff);
                LDSM_X4(bl0, bl1, bl2, bl3, uKl + boff);
                MMA_BF16(sacc[2*np],   ah, bh0, bh1);
                MMA_BF16(sacc[2*np],   ah, bl0, bl1);
                MMA_BF16(sacc[2*np],   al, bh0, bh1);
                MMA_BF16(sacc[2*np+1], ah, bh2, bh3);
                MMA_BF16(sacc[2*np+1], ah, bl2, bl3);
                MMA_BF16(sacc[2*np+1], al, bh2, bh3);
            }
        }

        // ---- scale + mask bias ----
        #pragma unroll
        for (int nt = 0; nt < 16; nt++) {
            float2 bv = *(const float2*)&mb[k0 + nt * 8 + (lane & 3) * 2];
            sacc[nt][0] = sacc[nt][0] * 0.125f + bv.x;
            sacc[nt][1] = sacc[nt][1] * 0.125f + bv.y;
            sacc[nt][2] = sacc[nt][2] * 0.125f + bv.x;
            sacc[nt][3] = sacc[nt][3] * 0.125f + bv.y;
        }

        // ---- online softmax ----
        float mx0 = -1e30f, mx1 = -1e30f;
        #pragma unroll
        for (int nt = 0; nt < 16; nt++) {
            mx0 = fmaxf(mx0, fmaxf(sacc[nt][0], sacc[nt][1]));
            mx1 = fmaxf(mx1, fmaxf(sacc[nt][2], sacc[nt][3]));
        }
        mx0 = fmaxf(mx0, __shfl_xor_sync(0xffffffffu, mx0, 1));
        mx0 = fmaxf(mx0, __shfl_xor_sync(0xffffffffu, mx0, 2));
        mx1 = fmaxf(mx1, __shfl_xor_sync(0xffffffffu, mx1, 1));
        mx1 = fmaxf(mx1, __shfl_xor_sync(0xffffffffu, mx1, 2));
        const float mn0 = fmaxf(mrun0, mx0);
        const float mn1 = fmaxf(mrun1, mx1);
        const float al0 = __expf(mrun0 - mn0);
        const float al1 = __expf(mrun1 - mn1);
        mrun0 = mn0; mrun1 = mn1;

        float sum0 = 0.f, sum1 = 0.f;
        #pragma unroll
        for (int nt = 0; nt < 16; nt++) {
            sacc[nt][0] = __expf(sacc[nt][0] - mn0); sum0 += sacc[nt][0];
            sacc[nt][1] = __expf(sacc[nt][1] - mn0); sum0 += sacc[nt][1];
            sacc[nt][2] = __expf(sacc[nt][2] - mn1); sum1 += sacc[nt][2];
            sacc[nt][3] = __expf(sacc[nt][3] - mn1); sum1 += sacc[nt][3];
        }
        sum0 += __shfl_xor_sync(0xffffffffu, sum0, 1);
        sum0 += __shfl_xor_sync(0xffffffffu, sum0, 2);
        sum1 += __shfl_xor_sync(0xffffffffu, sum1, 1);
        sum1 += __shfl_xor_sync(0xffffffffu, sum1, 2);
        lrun0 = lrun0 * al0 + sum0;
        lrun1 = lrun1 * al1 + sum1;

        #pragma unroll
        for (int nt = 0; nt < 8; nt++) {
            oacc[nt][0] *= al0; oacc[nt][1] *= al0;
            oacc[nt][2] *= al1; oacc[nt][3] *= al1;
        }

        // ---- O += P V : P fragments built in registers from sacc ----
        #pragma unroll
        for (int j = 0; j < 8; j++) {
            uint32_t ph[4], pl[4];
            float ra, rb;
            ph[0] = pack_bf(sacc[2*j][0],   sacc[2*j][1],   ra, rb); pl[0] = pack_bf_only(ra, rb);
            ph[1] = pack_bf(sacc[2*j][2],   sacc[2*j][3],   ra, rb); pl[1] = pack_bf_only(ra, rb);
            ph[2] = pack_bf(sacc[2*j+1][0], sacc[2*j+1][1], ra, rb); pl[2] = pack_bf_only(ra, rb);
            ph[3] = pack_bf(sacc[2*j+1][2], sacc[2*j+1][3], ra, rb); pl[3] = pack_bf_only(ra, rb);
            #pragma unroll
            for (int np = 0; np < 4; np++) {
                uint32_t boff = (uint32_t)(((np * 16 + bNad) * VST + j * 16 + bKh) * 2);
                uint32_t bh0, bh1, bh2, bh3, bl0, bl1, bl2, bl3;
                LDSM_X4(bh0, bh1, bh2, bh3, uVh + boff);
                LDSM_X4(bl0, bl1, bl2, bl3, uVl + boff);
                MMA_BF16(oacc[2*np],   ph, bh0, bh1);
                MMA_BF16(oacc[2*np],   ph, bl0, bl1);
                MMA_BF16(oacc[2*np],   pl, bh0, bh1);
                MMA_BF16(oacc[2*np+1], ph, bh2, bh3);
                MMA_BF16(oacc[2*np+1], ph, bl2, bl3);
                MMA_BF16(oacc[2*np+1], pl, bh2, bh3);
            }
        }
        __syncthreads();   // done reading stage t&1 before it is refilled at t+1's issue
    }

    // ---- write ctx ----
    const float inv0 = 1.f / lrun0;
    const float inv1 = 1.f / lrun1;
    const int r0g = q0 + wrow + (lane >> 2);
    const int r1g = r0g + 8;
    #pragma unroll
    for (int nt = 0; nt < 8; nt++) {
        const int c = h * DKn + nt * 8 + (lane & 3) * 2;
        *(float2*)(g_ctx + ((size_t)b * Sn + r0g) * Dn + c) =
            make_float2(oacc[nt][0] * inv0, oacc[nt][1] * inv0);
        *(float2*)(g_ctx + ((size_t)b * Sn + r1g) * Dn + c) =
            make_float2(oacc[nt][2] * inv1, oacc[nt][3] * inv1);
    }
}

// ---------------- LayerNorm over D=512 ----------------
__global__ __launch_bounds__(256)
void ln_kernel(const float* __restrict__ in, const float* __restrict__ g,
               const float* __restrict__ beta, float* __restrict__ out)
{
    const int row = blockIdx.x;
    const float* x = in + (size_t)row * Dn;
    const int tid = threadIdx.x;

    float v0 = x[tid], v1 = x[tid + 256];
    float s = v0 + v1;
    __shared__ float red[8];
    __shared__ float mu_s, rs_s;
    #pragma unroll
    for (int o = 16; o; o >>= 1) s += __shfl_xor_sync(0xffffffffu, s, o);
    if ((tid & 31) == 0) red[tid >> 5] = s;
    __syncthreads();
    if (tid == 0) {
        float t = 0.f;
        #pragma unroll
        for (int i = 0; i < 8; i++) t += red[i];
        mu_s = t * (1.0f / Dn);
    }
    __syncthreads();
    const float mu = mu_s;
    const float d0 = v0 - mu, d1 = v1 - mu;
    float vs = d0*d0 + d1*d1;
    #pragma unroll
    for (int o = 16; o; o >>= 1) vs += __shfl_xor_sync(0xffffffffu, vs, o);
    if ((tid & 31) == 0) red[tid >> 5] = vs;
    __syncthreads();
    if (tid == 0) {
        float t = 0.f;
        #pragma unroll
        for (int i = 0; i < 8; i++) t += red[i];
        rs_s = rsqrtf(t * (1.0f / Dn) + 1e-5f);
    }
    __syncthreads();
    const float rs = rs_s;
    out[(size_t)row * Dn + tid]       = d0 * rs * g[tid]       + beta[tid];
    out[(size_t)row * Dn + tid + 256] = d1 * rs * g[tid + 256] + beta[tid + 256];
}

// ---------------- launch ----------------
extern "C" void kernel_launch(void* const* d_in, const int* in_sizes, int n_in,
                              void* d_out, int out_size)
{
    const float* x   = (const float*)d_in[0];
    const int*   msk = (const int*)  d_in[1];
    const float* wq  = (const float*)d_in[2];
    const float* wk  = (const float*)d_in[3];
    const float* wv  = (const float*)d_in[4];
    const float* wo  = (const float*)d_in[5];
    const float* w1  = (const float*)d_in[6];
    const float* b1  = (const float*)d_in[7];
    const float* w2  = (const float*)d_in[8];
    const float* b2  = (const float*)d_in[9];
    const float* g1  = (const float*)d_in[10];
    const float* be1 = (const float*)d_in[11];
    const float* g2  = (const float*)d_in[12];
    const float* be2 = (const float*)d_in[13];
    float* out = (float*)d_out;

    uint16_t *qh, *ql, *kh, *kl, *vh, *vl;
    float *ctx, *res1, *x1, *ff;
    cudaGetSymbolAddress((void**)&qh,   g_qh);
    cudaGetSymbolAddress((void**)&ql,   g_ql);
    cudaGetSymbolAddress((void**)&kh,   g_kh);
    cudaGetSymbolAddress((void**)&kl,   g_kl);
    cudaGetSymbolAddress((void**)&vh,   g_vh);
    cudaGetSymbolAddress((void**)&vl,   g_vl);
    cudaGetSymbolAddress((void**)&ctx,  g_ctx);
    cudaGetSymbolAddress((void**)&res1, g_res1);
    cudaGetSymbolAddress((void**)&x1,   g_x1);
    cudaGetSymbolAddress((void**)&ff,   g_ff);

    cudaFuncSetAttribute(tc_gemm<Dn, Dn, EPI_QK_HL>,
                         cudaFuncAttributeMaxDynamicSharedMemorySize, HG_SMEM);
    cudaFuncSetAttribute(tc_gemm<Dn, Dn, EPI_V_HL>,
                         cudaFuncAttributeMaxDynamicSharedMemorySize, HG_SMEM);
    cudaFuncSetAttribute(tc_gemm<Dn, Dn, EPI_RES>,
                         cudaFuncAttributeMaxDynamicSharedMemorySize, HG_SMEM);
    cudaFuncSetAttribute(tc_gemm<DFFn, Dn, EPI_BIAS_RELU>,
                         cudaFuncAttributeMaxDynamicSharedMemorySize, HG_SMEM);
    cudaFuncSetAttribute(tc_gemm<Dn, DFFn, EPI_BIAS_RES>,
                         cudaFuncAttributeMaxDynamicSharedMemorySize, HG_SMEM);
    cudaFuncSetAttribute(attn_kernel,
                         cudaFuncAttributeMaxDynamicSharedMemorySize, ATT_SMEM);

    const dim3 blk(256);
    const dim3 g512(Dn/128,  Mrows/128);   // (4,64)
    const dim3 gff1(DFFn/128, Mrows/128);  // (16,64)

    // QKV projections -> bf16 hi/lo (Q/K: [B,H,S,DK]; V: [B,H,DK,S])
    tc_gemm<Dn, Dn, EPI_QK_HL><<<g512, blk, HG_SMEM>>>(x, wq, nullptr, nullptr, nullptr, qh, ql);
    tc_gemm<Dn, Dn, EPI_QK_HL><<<g512, blk, HG_SMEM>>>(x, wk, nullptr, nullptr, nullptr, kh, kl);
    tc_gemm<Dn, Dn, EPI_V_HL ><<<g512, blk, HG_SMEM>>>(x, wv, nullptr, nullptr, nullptr, vh, vl);

    // attention (HMMA, cp.async pipelined)
    attn_kernel<<<dim3(Sn/128, Hn, Bn), blk, ATT_SMEM>>>(msk);

    // attn_out projection + residual
    tc_gemm<Dn, Dn, EPI_RES><<<g512, blk, HG_SMEM>>>(ctx, wo, nullptr, x, res1, nullptr, nullptr);
    // LN1
    ln_kernel<<<Mrows, blk>>>(res1, g1, be1, x1);
    // FFN
    tc_gemm<DFFn, Dn, EPI_BIAS_RELU><<<gff1, blk, HG_SMEM>>>(x1, w1, b1, nullptr, ff, nullptr, nullptr);
    tc_gemm<Dn, DFFn, EPI_BIAS_RES><<<g512, blk, HG_SMEM>>>(ff, w2, b2, x1, res1, nullptr, nullptr);
    // LN2 -> out
    ln_kernel<<<Mrows, blk>>>(res1, g2, be2, out);
}